// round 4
// baseline (speedup 1.0000x reference)
#include <cuda_runtime.h>

#define S_LEN 2048
#define HID   2048
#define NH    16
#define NKH   8
#define HD    128
#define SCALE 0.08838834764831845f

#define Y_SIZE (S_LEN * NH * HD)

// Scratch (allocation-free rule: __device__ globals)
__device__ float g_q[S_LEN * NH * HD];     // 16 MB
__device__ float g_k[S_LEN * NKH * HD];    //  8 MB
__device__ float g_v[S_LEN * NKH * HD];    //  8 MB
__device__ float g_attn[S_LEN * NH * HD];  // 16 MB

// ---------------------------------------------------------------------------
// NT SGEMM: C[M,N] = A[M,K] * B[N,K]^T   (both row-major, K contiguous)
// 128x128 tile, BK=16, 256 threads, 8x8 microtile.
// M,N,K all multiples of 128/16 here -> no predication.
// ---------------------------------------------------------------------------
__global__ __launch_bounds__(256)
void sgemm_nt(const float* __restrict__ A, const float* __restrict__ B,
              float* __restrict__ C, int M, int N, int K)
{
    __shared__ float As[16][132];
    __shared__ float Bs[16][132];
    const int tid = threadIdx.x;
    const int bm = blockIdx.y, bn = blockIdx.x;
    const float* Ab = A + (size_t)bm * 128 * K;
    const float* Bb = B + (size_t)bn * 128 * K;
    const int lr = tid >> 2;          // 0..63
    const int lc = (tid & 3) << 2;    // 0,4,8,12
    const int ty = tid >> 4, tx = tid & 15;

    float acc[8][8];
#pragma unroll
    for (int i = 0; i < 8; i++)
#pragma unroll
        for (int j = 0; j < 8; j++) acc[i][j] = 0.f;

    for (int k0 = 0; k0 < K; k0 += 16) {
#pragma unroll
        for (int r = 0; r < 128; r += 64) {
            float4 va = *(const float4*)(Ab + (size_t)(lr + r) * K + k0 + lc);
            As[lc + 0][lr + r] = va.x;
            As[lc + 1][lr + r] = va.y;
            As[lc + 2][lr + r] = va.z;
            As[lc + 3][lr + r] = va.w;
            float4 vb = *(const float4*)(Bb + (size_t)(lr + r) * K + k0 + lc);
            Bs[lc + 0][lr + r] = vb.x;
            Bs[lc + 1][lr + r] = vb.y;
            Bs[lc + 2][lr + r] = vb.z;
            Bs[lc + 3][lr + r] = vb.w;
        }
        __syncthreads();
#pragma unroll
        for (int kk = 0; kk < 16; kk++) {
            float a[8], b[8];
            float4 t;
            t = *(const float4*)&As[kk][ty * 8];     a[0]=t.x; a[1]=t.y; a[2]=t.z; a[3]=t.w;
            t = *(const float4*)&As[kk][ty * 8 + 4]; a[4]=t.x; a[5]=t.y; a[6]=t.z; a[7]=t.w;
            t = *(const float4*)&Bs[kk][tx * 8];     b[0]=t.x; b[1]=t.y; b[2]=t.z; b[3]=t.w;
            t = *(const float4*)&Bs[kk][tx * 8 + 4]; b[4]=t.x; b[5]=t.y; b[6]=t.z; b[7]=t.w;
#pragma unroll
            for (int i = 0; i < 8; i++)
#pragma unroll
                for (int j = 0; j < 8; j++) acc[i][j] = fmaf(a[i], b[j], acc[i][j]);
        }
        __syncthreads();
    }
#pragma unroll
    for (int i = 0; i < 8; i++) {
        float* cp = C + (size_t)(bm * 128 + ty * 8 + i) * N + bn * 128 + tx * 8;
        *(float4*)cp       = make_float4(acc[i][0], acc[i][1], acc[i][2], acc[i][3]);
        *(float4*)(cp + 4) = make_float4(acc[i][4], acc[i][5], acc[i][6], acc[i][7]);
    }
}

// ---------------------------------------------------------------------------
// Fused per-head RMSNorm + RoPE, in place. grid = (S, num_heads), block = 128.
// x layout: [s][head][128]. freqs: [s][64].
// ---------------------------------------------------------------------------
__global__ __launch_bounds__(128)
void norm_rope_kernel(float* __restrict__ x, const float* __restrict__ w,
                      const float* __restrict__ fc, const float* __restrict__ fs,
                      int nheads)
{
    const int s = blockIdx.x, hh = blockIdx.y, d = threadIdx.x;
    float* row = x + ((size_t)s * nheads + hh) * HD;
    float v = row[d];
    float p = v * v;
#pragma unroll
    for (int o = 16; o > 0; o >>= 1) p += __shfl_xor_sync(0xffffffffu, p, o);
    __shared__ float ws[4];
    __shared__ float sx[128];
    const int lane = d & 31, wid = d >> 5;
    if (lane == 0) ws[wid] = p;
    __syncthreads();
    const float tot = ws[0] + ws[1] + ws[2] + ws[3];
    const float r = rsqrtf(tot * (1.0f / 128.0f) + 1e-6f);
    sx[d] = v * r * w[d];
    __syncthreads();
    const float c  = fc[s * 64 + (d & 63)];
    const float sn = fs[s * 64 + (d & 63)];
    float out;
    if (d < 64) out = sx[d] * c - sx[d + 64] * sn;
    else        out = sx[d - 64] * sn + sx[d] * c;
    row[d] = out;
}

// k_new (post-RoPE k, last token), v_new (raw v, last token)
__global__ void kvnew_kernel(const float* __restrict__ k, const float* __restrict__ v,
                             float* __restrict__ out)
{
    const int i = blockIdx.x * 256 + threadIdx.x;
    if (i < NKH * HD) {
        out[Y_SIZE + i]            = k[(size_t)(S_LEN - 1) * NKH * HD + i];
        out[Y_SIZE + NKH * HD + i] = v[(size_t)(S_LEN - 1) * NKH * HD + i];
    }
}

// ---------------------------------------------------------------------------
// Causal flash attention, fp32. BM=BN=64, 256 threads.
// grid = (S/64, H). GQA: kv head = h >> 1.
// Smem: Qs[d][m] 32KB, Ks[d][n] 32KB, Vs[n][d] 32KB, Ps[m][68] 17KB.
// ---------------------------------------------------------------------------
#define PSTR 68
#define FLASH_SMEM ((128 * 64 + 128 * 64 + 64 * 128 + 64 * PSTR) * sizeof(float))

__global__ __launch_bounds__(256)
void flash_kernel(const float* __restrict__ Q, const float* __restrict__ Kk,
                  const float* __restrict__ Vv, float* __restrict__ O)
{
    extern __shared__ float sm[];
    float* Qs = sm;                   // [128][64]
    float* Ks = sm + 128 * 64;        // [128][64]
    float* Vs = sm + 2 * 128 * 64;    // [64][128]
    float* Ps = sm + 3 * 128 * 64;    // [64][PSTR]

    const int qt = blockIdx.x, h = blockIdx.y;
    const int kh = h >> 1;
    const int qbase = qt * 64;
    const int tid = threadIdx.x;
    const int ty = tid >> 4, tx = tid & 15;
    const int m0 = ty * 4, n0 = tx * 4;
    const int d0 = tx * 8;

    // Load Q tile transposed: Qs[dd][m]
    {
        const int m = tid >> 2;
        const int c0 = (tid & 3) * 32;
        const float* qp = Q + ((size_t)(qbase + m) * NH + h) * HD + c0;
#pragma unroll
        for (int j = 0; j < 32; j += 4) {
            float4 t = *(const float4*)(qp + j);
            const int dd = c0 + j;
            Qs[(dd + 0) * 64 + m] = t.x;
            Qs[(dd + 1) * 64 + m] = t.y;
            Qs[(dd + 2) * 64 + m] = t.z;
            Qs[(dd + 3) * 64 + m] = t.w;
        }
    }

    float mrow[4], lrow[4], acc[4][8];
#pragma unroll
    for (int i = 0; i < 4; i++) { mrow[i] = -1e30f; lrow[i] = 0.f; }
#pragma unroll
    for (int i = 0; i < 4; i++)
#pragma unroll
        for (int j = 0; j < 8; j++) acc[i][j] = 0.f;

    for (int kt = 0; kt <= qt; kt++) {
        const int kbase = kt * 64;
        __syncthreads();   // previous iteration done reading Ks/Vs/Ps
        {
            const int n = tid >> 2;
            const int c0 = (tid & 3) * 32;
            const float* kp = Kk + ((size_t)(kbase + n) * NKH + kh) * HD + c0;
            const float* vp = Vv + ((size_t)(kbase + n) * NKH + kh) * HD + c0;
#pragma unroll
            for (int j = 0; j < 32; j += 4) {
                float4 t = *(const float4*)(kp + j);
                const int dd = c0 + j;
                Ks[(dd + 0) * 64 + n] = t.x;
                Ks[(dd + 1) * 64 + n] = t.y;
                Ks[(dd + 2) * 64 + n] = t.z;
                Ks[(dd + 3) * 64 + n] = t.w;
                *(float4*)(Vs + n * 128 + dd) = *(const float4*)(vp + j);
            }
        }
        __syncthreads();

        // scores: 4x4 per thread
        float sc[4][4];
#pragma unroll
        for (int i = 0; i < 4; i++)
#pragma unroll
            for (int j = 0; j < 4; j++) sc[i][j] = 0.f;
#pragma unroll 4
        for (int dd = 0; dd < 128; dd++) {
            float4 a = *(const float4*)(Qs + dd * 64 + m0);
            float4 b = *(const float4*)(Ks + dd * 64 + n0);
            float av[4] = {a.x, a.y, a.z, a.w};
            float bv[4] = {b.x, b.y, b.z, b.w};
#pragma unroll
            for (int i = 0; i < 4; i++)
#pragma unroll
                for (int j = 0; j < 4; j++) sc[i][j] = fmaf(av[i], bv[j], sc[i][j]);
        }

        // online softmax (row stats across the 16-lane tx group)
#pragma unroll
        for (int i = 0; i < 4; i++) {
#pragma unroll
            for (int j = 0; j < 4; j++) {
                float val = sc[i][j] * SCALE;
                if (kbase + n0 + j > qbase + m0 + i) val = -1e9f;
                sc[i][j] = val;
            }
            float tm = fmaxf(fmaxf(sc[i][0], sc[i][1]), fmaxf(sc[i][2], sc[i][3]));
            tm = fmaxf(tm, __shfl_xor_sync(0xffffffffu, tm, 1));
            tm = fmaxf(tm, __shfl_xor_sync(0xffffffffu, tm, 2));
            tm = fmaxf(tm, __shfl_xor_sync(0xffffffffu, tm, 4));
            tm = fmaxf(tm, __shfl_xor_sync(0xffffffffu, tm, 8));
            const float mnew = fmaxf(mrow[i], tm);
            const float corr = __expf(mrow[i] - mnew);
            float rs = 0.f;
#pragma unroll
            for (int j = 0; j < 4; j++) {
                const float e = __expf(sc[i][j] - mnew);
                sc[i][j] = e;
                rs += e;
            }
            rs += __shfl_xor_sync(0xffffffffu, rs, 1);
            rs += __shfl_xor_sync(0xffffffffu, rs, 2);
            rs += __shfl_xor_sync(0xffffffffu, rs, 4);
            rs += __shfl_xor_sync(0xffffffffu, rs, 8);
            lrow[i] = lrow[i] * corr + rs;
            mrow[i] = mnew;
#pragma unroll
            for (int j = 0; j < 8; j++) acc[i][j] *= corr;
            *(float4*)(Ps + (m0 + i) * PSTR + n0) =
                make_float4(sc[i][0], sc[i][1], sc[i][2], sc[i][3]);
        }
        __syncthreads();

        // O += P @ V  (each thread: 4 rows x 8 d-cols)
#pragma unroll 4
        for (int n = 0; n < 64; n++) {
            const float p0 = Ps[(m0 + 0) * PSTR + n];
            const float p1 = Ps[(m0 + 1) * PSTR + n];
            const float p2 = Ps[(m0 + 2) * PSTR + n];
            const float p3 = Ps[(m0 + 3) * PSTR + n];
            float4 v0 = *(const float4*)(Vs + n * 128 + d0);
            float4 v1 = *(const float4*)(Vs + n * 128 + d0 + 4);
            float vv[8] = {v0.x, v0.y, v0.z, v0.w, v1.x, v1.y, v1.z, v1.w};
#pragma unroll
            for (int j = 0; j < 8; j++) {
                acc[0][j] = fmaf(p0, vv[j], acc[0][j]);
                acc[1][j] = fmaf(p1, vv[j], acc[1][j]);
                acc[2][j] = fmaf(p2, vv[j], acc[2][j]);
                acc[3][j] = fmaf(p3, vv[j], acc[3][j]);
            }
        }
    }

#pragma unroll
    for (int i = 0; i < 4; i++) {
        const float inv = 1.0f / lrow[i];
        float* op = O + ((size_t)(qbase + m0 + i) * NH + h) * HD + d0;
        *(float4*)op       = make_float4(acc[i][0]*inv, acc[i][1]*inv, acc[i][2]*inv, acc[i][3]*inv);
        *(float4*)(op + 4) = make_float4(acc[i][4]*inv, acc[i][5]*inv, acc[i][6]*inv, acc[i][7]*inv);
    }
}

// ---------------------------------------------------------------------------
extern "C" void kernel_launch(void* const* d_in, const int* in_sizes, int n_in,
                              void* d_out, int out_size)
{
    const float* X  = (const float*)d_in[0];  // hidden_states [2048,2048]
    const float* fc = (const float*)d_in[1];  // freqs_cos [2048,64]
    const float* fs = (const float*)d_in[2];  // freqs_sin [2048,64]
    // d_in[3] atten_mask unused: exactly causal, applied analytically
    const float* Wq = (const float*)d_in[4];
    const float* Wk = (const float*)d_in[5];
    const float* Wv = (const float*)d_in[6];
    const float* Wo = (const float*)d_in[7];
    const float* qw = (const float*)d_in[8];
    const float* kw = (const float*)d_in[9];
    float* out = (float*)d_out;

    float *q, *k, *v, *attn;
    cudaGetSymbolAddress((void**)&q, g_q);
    cudaGetSymbolAddress((void**)&k, g_k);
    cudaGetSymbolAddress((void**)&v, g_v);
    cudaGetSymbolAddress((void**)&attn, g_attn);

    cudaFuncSetAttribute(flash_kernel, cudaFuncAttributeMaxDynamicSharedMemorySize,
                         (int)FLASH_SMEM);

    // QKV projections (NT gemms)
    sgemm_nt<<<dim3(16, 16), 256>>>(X, Wq, q, S_LEN, NH * HD, HID);
    sgemm_nt<<<dim3(8, 16),  256>>>(X, Wk, k, S_LEN, NKH * HD, HID);
    sgemm_nt<<<dim3(8, 16),  256>>>(X, Wv, v, S_LEN, NKH * HD, HID);

    // per-head RMSNorm + RoPE (in place)
    norm_rope_kernel<<<dim3(S_LEN, NH),  128>>>(q, qw, fc, fs, NH);
    norm_rope_kernel<<<dim3(S_LEN, NKH), 128>>>(k, kw, fc, fs, NKH);

    // k_new / v_new tail outputs
    kvnew_kernel<<<4, 256>>>(k, v, out);

    // causal flash attention
    flash_kernel<<<dim3(S_LEN / 64, NH), 256, FLASH_SMEM>>>(q, k, v, attn);

    // output projection directly into d_out
    sgemm_nt<<<dim3(16, 16), 256>>>(attn, Wo, out, S_LEN, HID, NH * HD);
}

// round 11
// speedup vs baseline: 1.4925x; 1.4925x over previous
#include <cuda_runtime.h>
#include <cuda_bf16.h>
#include <cstdint>

typedef __nv_bfloat16 bf16;

#define S_LEN 2048
#define HID   2048
#define NH    16
#define NKH   8
#define HD    128
#define SCALE 0.08838834764831845f
#define Y_SIZE (S_LEN * NH * HD)

// ---------------- fp32 scratch ----------------
__device__ float g_q[S_LEN * NH * HD];     // 16 MB
__device__ float g_k[S_LEN * NKH * HD];    //  8 MB
__device__ float g_v[S_LEN * NKH * HD];    //  8 MB
__device__ float g_attn[S_LEN * NH * HD];  // 16 MB

// ---------------- bf16 split arena (hi/lo pairs) ----------------
#define OFF_XH   0u
#define OFF_XL   4194304u
#define OFF_WQH  8388608u
#define OFF_WQL  12582912u
#define OFF_WKH  16777216u
#define OFF_WKL  18874368u
#define OFF_WVH  20971520u
#define OFF_WVL  23068672u
#define OFF_WOH  25165824u
#define OFF_WOL  29360128u
#define OFF_ATH  33554432u
#define OFF_ATL  37748736u
__device__ __align__(1024) bf16 g_bf[41943040];

__device__ __forceinline__ uint32_t smem_u32(const void* p) {
    uint32_t a;
    asm("{ .reg .u64 t; cvta.to.shared.u64 t, %1; cvt.u32.u64 %0, t; }"
        : "=r"(a) : "l"(p));
    return a;
}

// ---------------------------------------------------------------------------
// split fp32 -> bf16 hi + bf16 lo
// ---------------------------------------------------------------------------
__global__ __launch_bounds__(256)
void split_bf16(const float* __restrict__ x, bf16* __restrict__ hi,
                bf16* __restrict__ lo, int n)
{
    int i = blockIdx.x * 256 + threadIdx.x;
    if (i < n) {
        float v = x[i];
        bf16 h = __float2bfloat16(v);
        hi[i] = h;
        lo[i] = __float2bfloat16(v - __bfloat162float(h));
    }
}

// ---------------------------------------------------------------------------
// HMMA NT GEMM (mma.sync m16n8k16 bf16, 3-term split, fp32 accum).
// C[M,N] = A[M,K] * B[N,K]^T. 128x128 CTA tile, 8 warps (2x4), 64x32/warp.
// K chunk = 64. SMEM: 4 tiles [128][72] bf16 (pad 8 -> conflict-free ldmatrix).
// Family-target-safe: no tcgen05 / no 'a'-suffix features.
// ---------------------------------------------------------------------------
#define GSTR 72
#define MG_SMEM (4 * 128 * GSTR * 2)

__device__ __forceinline__ void ldsm4(uint32_t* r, uint32_t addr) {
    asm volatile("ldmatrix.sync.aligned.m8n8.x4.shared.b16 {%0,%1,%2,%3}, [%4];"
                 : "=r"(r[0]), "=r"(r[1]), "=r"(r[2]), "=r"(r[3]) : "r"(addr));
}
__device__ __forceinline__ void mma16816(float* c, const uint32_t* a, const uint32_t* b) {
    asm volatile("mma.sync.aligned.m16n8k16.row.col.f32.bf16.bf16.f32 "
                 "{%0,%1,%2,%3}, {%4,%5,%6,%7}, {%8,%9}, {%0,%1,%2,%3};"
                 : "+f"(c[0]), "+f"(c[1]), "+f"(c[2]), "+f"(c[3])
                 : "r"(a[0]), "r"(a[1]), "r"(a[2]), "r"(a[3]), "r"(b[0]), "r"(b[1]));
}

__global__ __launch_bounds__(256)
void mma_gemm(const bf16* __restrict__ Ahi, const bf16* __restrict__ Alo,
              const bf16* __restrict__ Bhi, const bf16* __restrict__ Blo,
              float* __restrict__ C, int M, int N, int K)
{
    extern __shared__ bf16 smb[];
    bf16* sAh = smb;
    bf16* sAl = smb + 128 * GSTR;
    bf16* sBh = smb + 2 * 128 * GSTR;
    bf16* sBl = smb + 3 * 128 * GSTR;

    const int tid = threadIdx.x;
    const int wid = tid >> 5, lane = tid & 31;
    const int warp_m = wid >> 2, warp_n = wid & 3;   // 2 x 4
    const int bm = blockIdx.y, bn = blockIdx.x;

    const bf16* gAh = Ahi + (size_t)bm * 128 * K;
    const bf16* gAl = Alo + (size_t)bm * 128 * K;
    const bf16* gBh = Bhi + (size_t)bn * 128 * K;
    const bf16* gBl = Blo + (size_t)bn * 128 * K;

    const uint32_t baAh = smem_u32(sAh), baAl = smem_u32(sAl);
    const uint32_t baBh = smem_u32(sBh), baBl = smem_u32(sBl);

    // ldmatrix per-lane address pieces (in bf16 elements, x2 for bytes later)
    // A (m16,k16): row = mb + (lane&15), k-half = lane>>4
    const int a_row = lane & 15, a_kh = (lane >> 4) << 3;
    // B (two n8 frags, k16): row = nb + (lane&7) + ((lane>>4)<<3), k-half = ((lane>>3)&1)
    const int b_row = (lane & 7) + ((lane >> 4) << 3), b_kh = ((lane >> 3) & 1) << 3;

    float acc[4][4][4];
#pragma unroll
    for (int i = 0; i < 4; i++)
#pragma unroll
        for (int j = 0; j < 4; j++)
#pragma unroll
            for (int r = 0; r < 4; r++) acc[i][j][r] = 0.f;

    const int NC = K >> 6;
    for (int c = 0; c < NC; c++) {
        const int k0 = c << 6;
        // load 4 tiles [128 rows][64 bf16]
#pragma unroll
        for (int i = 0; i < 4; i++) {
            const int u = tid + (i << 8);
            const int row = u >> 3, c8 = (u & 7) << 3;
            const size_t g = (size_t)row * K + k0 + c8;
            const int so = row * GSTR + c8;
            *(uint4*)(sAh + so) = *(const uint4*)(gAh + g);
            *(uint4*)(sAl + so) = *(const uint4*)(gAl + g);
            *(uint4*)(sBh + so) = *(const uint4*)(gBh + g);
            *(uint4*)(sBl + so) = *(const uint4*)(gBl + g);
        }
        __syncthreads();

#pragma unroll
        for (int ks = 0; ks < 4; ks++) {
            const int kk = ks << 4;
            uint32_t ah[4][4], al[4][4], bh[4][2], bl[4][2];
#pragma unroll
            for (int fm = 0; fm < 4; fm++) {
                const int mb = warp_m * 64 + fm * 16;
                const uint32_t off = ((mb + a_row) * GSTR + kk + a_kh) * 2;
                ldsm4(ah[fm], baAh + off);
                ldsm4(al[fm], baAl + off);
            }
#pragma unroll
            for (int fp = 0; fp < 2; fp++) {
                const int nb = warp_n * 32 + fp * 16;
                const uint32_t off = ((nb + b_row) * GSTR + kk + b_kh) * 2;
                uint32_t t[4];
                ldsm4(t, baBh + off);
                bh[2*fp][0] = t[0]; bh[2*fp][1] = t[1];
                bh[2*fp+1][0] = t[2]; bh[2*fp+1][1] = t[3];
                ldsm4(t, baBl + off);
                bl[2*fp][0] = t[0]; bl[2*fp][1] = t[1];
                bl[2*fp+1][0] = t[2]; bl[2*fp+1][1] = t[3];
            }
#pragma unroll
            for (int fm = 0; fm < 4; fm++)
#pragma unroll
                for (int fn = 0; fn < 4; fn++) {
                    mma16816(acc[fm][fn], ah[fm], bh[fn]);
                    mma16816(acc[fm][fn], ah[fm], bl[fn]);
                    mma16816(acc[fm][fn], al[fm], bh[fn]);
                }
        }
        __syncthreads();
    }

    // epilogue: c0,c1 -> (row, col), c2,c3 -> (row+8, col)
    const int rbase = bm * 128 + warp_m * 64 + (lane >> 2);
    const int cbase = bn * 128 + warp_n * 32 + ((lane & 3) << 1);
#pragma unroll
    for (int fm = 0; fm < 4; fm++) {
        const int row = rbase + fm * 16;
#pragma unroll
        for (int fn = 0; fn < 4; fn++) {
            const int col = cbase + fn * 8;
            *(float2*)(C + (size_t)row * N + col) =
                make_float2(acc[fm][fn][0], acc[fm][fn][1]);
            *(float2*)(C + (size_t)(row + 8) * N + col) =
                make_float2(acc[fm][fn][2], acc[fm][fn][3]);
        }
    }
}

// ---------------------------------------------------------------------------
// Fused per-head RMSNorm + RoPE, in place. grid = (S, num_heads), block = 128.
// ---------------------------------------------------------------------------
__global__ __launch_bounds__(128)
void norm_rope_kernel(float* __restrict__ x, const float* __restrict__ w,
                      const float* __restrict__ fc, const float* __restrict__ fs,
                      int nheads)
{
    const int s = blockIdx.x, hh = blockIdx.y, d = threadIdx.x;
    float* row = x + ((size_t)s * nheads + hh) * HD;
    float v = row[d];
    float p = v * v;
#pragma unroll
    for (int o = 16; o > 0; o >>= 1) p += __shfl_xor_sync(0xffffffffu, p, o);
    __shared__ float ws[4];
    __shared__ float sx[128];
    const int lane = d & 31, wid = d >> 5;
    if (lane == 0) ws[wid] = p;
    __syncthreads();
    const float tot = ws[0] + ws[1] + ws[2] + ws[3];
    const float r = rsqrtf(tot * (1.0f / 128.0f) + 1e-6f);
    sx[d] = v * r * w[d];
    __syncthreads();
    const float c  = fc[s * 64 + (d & 63)];
    const float sn = fs[s * 64 + (d & 63)];
    float out;
    if (d < 64) out = sx[d] * c - sx[d + 64] * sn;
    else        out = sx[d - 64] * sn + sx[d] * c;
    row[d] = out;
}

// k_new (post-RoPE k, last token), v_new (raw v, last token)
__global__ void kvnew_kernel(const float* __restrict__ k, const float* __restrict__ v,
                             float* __restrict__ out)
{
    const int i = blockIdx.x * 256 + threadIdx.x;
    if (i < NKH * HD) {
        out[Y_SIZE + i]            = k[(size_t)(S_LEN - 1) * NKH * HD + i];
        out[Y_SIZE + NKH * HD + i] = v[(size_t)(S_LEN - 1) * NKH * HD + i];
    }
}

// ---------------------------------------------------------------------------
// Causal flash attention, fp32. BM=BN=64, 256 threads. grid=(S/64, H).
// ---------------------------------------------------------------------------
#define PSTR 68
#define FLASH_SMEM ((128 * 64 + 128 * 64 + 64 * 128 + 64 * PSTR) * sizeof(float))

__global__ __launch_bounds__(256)
void flash_kernel(const float* __restrict__ Q, const float* __restrict__ Kk,
                  const float* __restrict__ Vv, float* __restrict__ O)
{
    extern __shared__ float smf[];
    float* Qs = smf;
    float* Ks = smf + 128 * 64;
    float* Vs = smf + 2 * 128 * 64;
    float* Ps = smf + 3 * 128 * 64;

    const int qt = blockIdx.x, h = blockIdx.y;
    const int kh = h >> 1;
    const int qbase = qt * 64;
    const int tid = threadIdx.x;
    const int ty = tid >> 4, tx = tid & 15;
    const int m0 = ty * 4, n0 = tx * 4;
    const int d0 = tx * 8;

    {
        const int m = tid >> 2;
        const int c0 = (tid & 3) * 32;
        const float* qp = Q + ((size_t)(qbase + m) * NH + h) * HD + c0;
#pragma unroll
        for (int j = 0; j < 32; j += 4) {
            float4 t = *(const float4*)(qp + j);
            const int dd = c0 + j;
            Qs[(dd + 0) * 64 + m] = t.x;
            Qs[(dd + 1) * 64 + m] = t.y;
            Qs[(dd + 2) * 64 + m] = t.z;
            Qs[(dd + 3) * 64 + m] = t.w;
        }
    }

    float mrow[4], lrow[4], acc[4][8];
#pragma unroll
    for (int i = 0; i < 4; i++) { mrow[i] = -1e30f; lrow[i] = 0.f; }
#pragma unroll
    for (int i = 0; i < 4; i++)
#pragma unroll
        for (int j = 0; j < 8; j++) acc[i][j] = 0.f;

    for (int kt = 0; kt <= qt; kt++) {
        const int kbase = kt * 64;
        __syncthreads();
        {
            const int n = tid >> 2;
            const int c0 = (tid & 3) * 32;
            const float* kp = Kk + ((size_t)(kbase + n) * NKH + kh) * HD + c0;
            const float* vp = Vv + ((size_t)(kbase + n) * NKH + kh) * HD + c0;
#pragma unroll
            for (int j = 0; j < 32; j += 4) {
                float4 t = *(const float4*)(kp + j);
                const int dd = c0 + j;
                Ks[(dd + 0) * 64 + n] = t.x;
                Ks[(dd + 1) * 64 + n] = t.y;
                Ks[(dd + 2) * 64 + n] = t.z;
                Ks[(dd + 3) * 64 + n] = t.w;
                *(float4*)(Vs + n * 128 + dd) = *(const float4*)(vp + j);
            }
        }
        __syncthreads();

        float sc[4][4];
#pragma unroll
        for (int i = 0; i < 4; i++)
#pragma unroll
            for (int j = 0; j < 4; j++) sc[i][j] = 0.f;
#pragma unroll 4
        for (int dd = 0; dd < 128; dd++) {
            float4 a = *(const float4*)(Qs + dd * 64 + m0);
            float4 b = *(const float4*)(Ks + dd * 64 + n0);
            float av[4] = {a.x, a.y, a.z, a.w};
            float bv[4] = {b.x, b.y, b.z, b.w};
#pragma unroll
            for (int i = 0; i < 4; i++)
#pragma unroll
                for (int j = 0; j < 4; j++) sc[i][j] = fmaf(av[i], bv[j], sc[i][j]);
        }

#pragma unroll
        for (int i = 0; i < 4; i++) {
#pragma unroll
            for (int j = 0; j < 4; j++) {
                float val = sc[i][j] * SCALE;
                if (kbase + n0 + j > qbase + m0 + i) val = -1e9f;
                sc[i][j] = val;
            }
            float tm = fmaxf(fmaxf(sc[i][0], sc[i][1]), fmaxf(sc[i][2], sc[i][3]));
            tm = fmaxf(tm, __shfl_xor_sync(0xffffffffu, tm, 1));
            tm = fmaxf(tm, __shfl_xor_sync(0xffffffffu, tm, 2));
            tm = fmaxf(tm, __shfl_xor_sync(0xffffffffu, tm, 4));
            tm = fmaxf(tm, __shfl_xor_sync(0xffffffffu, tm, 8));
            const float mnew = fmaxf(mrow[i], tm);
            const float corr = __expf(mrow[i] - mnew);
            float rs = 0.f;
#pragma unroll
            for (int j = 0; j < 4; j++) {
                const float e = __expf(sc[i][j] - mnew);
                sc[i][j] = e;
                rs += e;
            }
            rs += __shfl_xor_sync(0xffffffffu, rs, 1);
            rs += __shfl_xor_sync(0xffffffffu, rs, 2);
            rs += __shfl_xor_sync(0xffffffffu, rs, 4);
            rs += __shfl_xor_sync(0xffffffffu, rs, 8);
            lrow[i] = lrow[i] * corr + rs;
            mrow[i] = mnew;
#pragma unroll
            for (int j = 0; j < 8; j++) acc[i][j] *= corr;
            *(float4*)(Ps + (m0 + i) * PSTR + n0) =
                make_float4(sc[i][0], sc[i][1], sc[i][2], sc[i][3]);
        }
        __syncthreads();

#pragma unroll 4
        for (int n = 0; n < 64; n++) {
            const float p0 = Ps[(m0 + 0) * PSTR + n];
            const float p1 = Ps[(m0 + 1) * PSTR + n];
            const float p2 = Ps[(m0 + 2) * PSTR + n];
            const float p3 = Ps[(m0 + 3) * PSTR + n];
            float4 v0 = *(const float4*)(Vs + n * 128 + d0);
            float4 v1 = *(const float4*)(Vs + n * 128 + d0 + 4);
            float vv[8] = {v0.x, v0.y, v0.z, v0.w, v1.x, v1.y, v1.z, v1.w};
#pragma unroll
            for (int j = 0; j < 8; j++) {
                acc[0][j] = fmaf(p0, vv[j], acc[0][j]);
                acc[1][j] = fmaf(p1, vv[j], acc[1][j]);
                acc[2][j] = fmaf(p2, vv[j], acc[2][j]);
                acc[3][j] = fmaf(p3, vv[j], acc[3][j]);
            }
        }
    }

#pragma unroll
    for (int i = 0; i < 4; i++) {
        const float inv = 1.0f / lrow[i];
        float* op = O + ((size_t)(qbase + m0 + i) * NH + h) * HD + d0;
        *(float4*)op       = make_float4(acc[i][0]*inv, acc[i][1]*inv, acc[i][2]*inv, acc[i][3]*inv);
        *(float4*)(op + 4) = make_float4(acc[i][4]*inv, acc[i][5]*inv, acc[i][6]*inv, acc[i][7]*inv);
    }
}

// ---------------------------------------------------------------------------
extern "C" void kernel_launch(void* const* d_in, const int* in_sizes, int n_in,
                              void* d_out, int out_size)
{
    const float* X  = (const float*)d_in[0];
    const float* fc = (const float*)d_in[1];
    const float* fs = (const float*)d_in[2];
    // d_in[3] atten_mask unused: exactly causal, applied analytically
    const float* Wq = (const float*)d_in[4];
    const float* Wk = (const float*)d_in[5];
    const float* Wv = (const float*)d_in[6];
    const float* Wo = (const float*)d_in[7];
    const float* qw = (const float*)d_in[8];
    const float* kw = (const float*)d_in[9];
    float* out = (float*)d_out;

    float *q, *k, *v, *attn;
    bf16* bf;
    cudaGetSymbolAddress((void**)&q, g_q);
    cudaGetSymbolAddress((void**)&k, g_k);
    cudaGetSymbolAddress((void**)&v, g_v);
    cudaGetSymbolAddress((void**)&attn, g_attn);
    cudaGetSymbolAddress((void**)&bf, g_bf);

    cudaFuncSetAttribute(flash_kernel, cudaFuncAttributeMaxDynamicSharedMemorySize,
                         (int)FLASH_SMEM);
    cudaFuncSetAttribute(mma_gemm, cudaFuncAttributeMaxDynamicSharedMemorySize,
                         MG_SMEM);

    // fp32 -> bf16 hi/lo splits
    const int NB = 4194304, NS = 2097152;
    split_bf16<<<NB / 256, 256>>>(X,  bf + OFF_XH,  bf + OFF_XL,  NB);
    split_bf16<<<NB / 256, 256>>>(Wq, bf + OFF_WQH, bf + OFF_WQL, NB);
    split_bf16<<<NS / 256, 256>>>(Wk, bf + OFF_WKH, bf + OFF_WKL, NS);
    split_bf16<<<NS / 256, 256>>>(Wv, bf + OFF_WVH, bf + OFF_WVL, NS);
    split_bf16<<<NB / 256, 256>>>(Wo, bf + OFF_WOH, bf + OFF_WOL, NB);

    // QKV projections on tensor cores (HMMA, 3-term bf16 split)
    mma_gemm<<<dim3(16, 16), 256, MG_SMEM>>>(bf + OFF_XH, bf + OFF_XL,
                                             bf + OFF_WQH, bf + OFF_WQL,
                                             q, S_LEN, NH * HD, HID);
    mma_gemm<<<dim3(8, 16), 256, MG_SMEM>>>(bf + OFF_XH, bf + OFF_XL,
                                            bf + OFF_WKH, bf + OFF_WKL,
                                            k, S_LEN, NKH * HD, HID);
    mma_gemm<<<dim3(8, 16), 256, MG_SMEM>>>(bf + OFF_XH, bf + OFF_XL,
                                            bf + OFF_WVH, bf + OFF_WVL,
                                            v, S_LEN, NKH * HD, HID);

    // per-head RMSNorm + RoPE (in place)
    norm_rope_kernel<<<dim3(S_LEN, NH),  128>>>(q, qw, fc, fs, NH);
    norm_rope_kernel<<<dim3(S_LEN, NKH), 128>>>(k, kw, fc, fs, NKH);

    // k_new / v_new tail outputs
    kvnew_kernel<<<4, 256>>>(k, v, out);

    // causal flash attention (fp32)
    flash_kernel<<<dim3(S_LEN / 64, NH), 256, FLASH_SMEM>>>(q, k, v, attn);

    // output projection on tensor cores, directly into d_out
    split_bf16<<<NB / 256, 256>>>(attn, bf + OFF_ATH, bf + OFF_ATL, NB);
    mma_gemm<<<dim3(16, 16), 256, MG_SMEM>>>(bf + OFF_ATH, bf + OFF_ATL,
                                             bf + OFF_WOH, bf + OFF_WOL,
                                             out, S_LEN, HID, NH * HD);
}

// round 12
// speedup vs baseline: 2.9465x; 1.9741x over previous
#include <cuda_runtime.h>
#include <cuda_bf16.h>
#include <cstdint>

typedef __nv_bfloat16 bf16;

#define S_LEN 2048
#define HID   2048
#define NH    16
#define NKH   8
#define HD    128
#define SCALE 0.08838834764831845f
#define Y_SIZE (S_LEN * NH * HD)

// ---------------- fp32 scratch ----------------
__device__ float g_q[S_LEN * NH * HD];     // 16 MB
__device__ float g_k[S_LEN * NKH * HD];    //  8 MB
__device__ float g_v[S_LEN * NKH * HD];    //  8 MB
__device__ float g_attn[S_LEN * NH * HD];  // 16 MB

// ---------------- bf16 split arena #1 (gemm operands) ----------------
#define OFF_XH   0u
#define OFF_XL   4194304u
#define OFF_WQH  8388608u
#define OFF_WQL  12582912u
#define OFF_WKH  16777216u
#define OFF_WKL  18874368u
#define OFF_WVH  20971520u
#define OFF_WVL  23068672u
#define OFF_WOH  25165824u
#define OFF_WOL  29360128u
#define OFF_ATH  33554432u
#define OFF_ATL  37748736u
__device__ __align__(1024) bf16 g_bf[41943040];

// ---------------- bf16 split arena #2 (flash operands) ----------------
#define OFF_QH   0u
#define OFF_QL   4194304u
#define OFF_KH   8388608u
#define OFF_KL   10485760u
#define OFF_VTH  12582912u        // [kh][d][s] transposed
#define OFF_VTL  14680064u
__device__ __align__(1024) bf16 g_bf2[16777216];

__device__ __forceinline__ uint32_t smem_u32(const void* p) {
    uint32_t a;
    asm("{ .reg .u64 t; cvta.to.shared.u64 t, %1; cvt.u32.u64 %0, t; }"
        : "=r"(a) : "l"(p));
    return a;
}
__device__ __forceinline__ void ldsm4(uint32_t* r, uint32_t addr) {
    asm volatile("ldmatrix.sync.aligned.m8n8.x4.shared.b16 {%0,%1,%2,%3}, [%4];"
                 : "=r"(r[0]), "=r"(r[1]), "=r"(r[2]), "=r"(r[3]) : "r"(addr));
}
__device__ __forceinline__ void mma16816(float* c, const uint32_t* a, const uint32_t* b) {
    asm volatile("mma.sync.aligned.m16n8k16.row.col.f32.bf16.bf16.f32 "
                 "{%0,%1,%2,%3}, {%4,%5,%6,%7}, {%8,%9}, {%0,%1,%2,%3};"
                 : "+f"(c[0]), "+f"(c[1]), "+f"(c[2]), "+f"(c[3])
                 : "r"(a[0]), "r"(a[1]), "r"(a[2]), "r"(a[3]), "r"(b[0]), "r"(b[1]));
}
// pack two floats into bf16x2 hi + bf16x2 lo (a -> low half, b -> high half)
__device__ __forceinline__ void split2(float a, float b, uint32_t& h, uint32_t& l) {
    bf16 ha = __float2bfloat16(a), hb = __float2bfloat16(b);
    float la = a - __bfloat162float(ha), lb = b - __bfloat162float(hb);
    __nv_bfloat162 hv(ha, hb);
    __nv_bfloat162 lv = __floats2bfloat162_rn(la, lb);
    h = *(uint32_t*)&hv;
    l = *(uint32_t*)&lv;
}

// ---------------------------------------------------------------------------
// split fp32 -> bf16 hi + bf16 lo
// ---------------------------------------------------------------------------
__global__ __launch_bounds__(256)
void split_bf16(const float* __restrict__ x, bf16* __restrict__ hi,
                bf16* __restrict__ lo, int n)
{
    int i = blockIdx.x * 256 + threadIdx.x;
    if (i < n) {
        float v = x[i];
        bf16 h = __float2bfloat16(v);
        hi[i] = h;
        lo[i] = __float2bfloat16(v - __bfloat162float(h));
    }
}

// ---------------------------------------------------------------------------
// V transpose + split: g_v [s][kh][128] fp32 -> vt [kh][128][2048] bf16 hi/lo
// grid (64, 4, 8), block (32, 8)
// ---------------------------------------------------------------------------
__global__ __launch_bounds__(256)
void vtrans_split(const float* __restrict__ v, bf16* __restrict__ vh,
                  bf16* __restrict__ vl)
{
    __shared__ float t[32][33];
    const int s0 = blockIdx.x * 32, d0 = blockIdx.y * 32, kh = blockIdx.z;
#pragma unroll
    for (int i = 0; i < 4; i++) {
        const int row = s0 + threadIdx.y + i * 8;
        t[threadIdx.y + i * 8][threadIdx.x] =
            v[((size_t)row * NKH + kh) * HD + d0 + threadIdx.x];
    }
    __syncthreads();
#pragma unroll
    for (int i = 0; i < 4; i++) {
        const int d = d0 + threadIdx.y + i * 8;
        const int s = s0 + threadIdx.x;
        float val = t[threadIdx.x][threadIdx.y + i * 8];
        bf16 h = __float2bfloat16(val);
        const size_t o = ((size_t)kh * HD + d) * S_LEN + s;
        vh[o] = h;
        vl[o] = __float2bfloat16(val - __bfloat162float(h));
    }
}

// ---------------------------------------------------------------------------
// HMMA NT GEMM (mma.sync m16n8k16 bf16, 3-term split, fp32 accum).
// ---------------------------------------------------------------------------
#define GSTR 72
#define MG_SMEM (4 * 128 * GSTR * 2)

__global__ __launch_bounds__(256)
void mma_gemm(const bf16* __restrict__ Ahi, const bf16* __restrict__ Alo,
              const bf16* __restrict__ Bhi, const bf16* __restrict__ Blo,
              float* __restrict__ C, int M, int N, int K)
{
    extern __shared__ bf16 smb[];
    bf16* sAh = smb;
    bf16* sAl = smb + 128 * GSTR;
    bf16* sBh = smb + 2 * 128 * GSTR;
    bf16* sBl = smb + 3 * 128 * GSTR;

    const int tid = threadIdx.x;
    const int wid = tid >> 5, lane = tid & 31;
    const int warp_m = wid >> 2, warp_n = wid & 3;
    const int bm = blockIdx.y, bn = blockIdx.x;

    const bf16* gAh = Ahi + (size_t)bm * 128 * K;
    const bf16* gAl = Alo + (size_t)bm * 128 * K;
    const bf16* gBh = Bhi + (size_t)bn * 128 * K;
    const bf16* gBl = Blo + (size_t)bn * 128 * K;

    const uint32_t baAh = smem_u32(sAh), baAl = smem_u32(sAl);
    const uint32_t baBh = smem_u32(sBh), baBl = smem_u32(sBl);

    const int a_row = lane & 15, a_kh = (lane >> 4) << 3;
    const int b_row = (lane & 7) + ((lane >> 4) << 3), b_kh = ((lane >> 3) & 1) << 3;

    float acc[4][4][4];
#pragma unroll
    for (int i = 0; i < 4; i++)
#pragma unroll
        for (int j = 0; j < 4; j++)
#pragma unroll
            for (int r = 0; r < 4; r++) acc[i][j][r] = 0.f;

    const int NC = K >> 6;
    for (int c = 0; c < NC; c++) {
        const int k0 = c << 6;
#pragma unroll
        for (int i = 0; i < 4; i++) {
            const int u = tid + (i << 8);
            const int row = u >> 3, c8 = (u & 7) << 3;
            const size_t g = (size_t)row * K + k0 + c8;
            const int so = row * GSTR + c8;
            *(uint4*)(sAh + so) = *(const uint4*)(gAh + g);
            *(uint4*)(sAl + so) = *(const uint4*)(gAl + g);
            *(uint4*)(sBh + so) = *(const uint4*)(gBh + g);
            *(uint4*)(sBl + so) = *(const uint4*)(gBl + g);
        }
        __syncthreads();

#pragma unroll
        for (int ks = 0; ks < 4; ks++) {
            const int kk = ks << 4;
            uint32_t ah[4][4], al[4][4], bh[4][2], bl[4][2];
#pragma unroll
            for (int fm = 0; fm < 4; fm++) {
                const int mb = warp_m * 64 + fm * 16;
                const uint32_t off = ((mb + a_row) * GSTR + kk + a_kh) * 2;
                ldsm4(ah[fm], baAh + off);
                ldsm4(al[fm], baAl + off);
            }
#pragma unroll
            for (int fp = 0; fp < 2; fp++) {
                const int nb = warp_n * 32 + fp * 16;
                const uint32_t off = ((nb + b_row) * GSTR + kk + b_kh) * 2;
                uint32_t t[4];
                ldsm4(t, baBh + off);
                bh[2*fp][0] = t[0]; bh[2*fp][1] = t[1];
                bh[2*fp+1][0] = t[2]; bh[2*fp+1][1] = t[3];
                ldsm4(t, baBl + off);
                bl[2*fp][0] = t[0]; bl[2*fp][1] = t[1];
                bl[2*fp+1][0] = t[2]; bl[2*fp+1][1] = t[3];
            }
#pragma unroll
            for (int fm = 0; fm < 4; fm++)
#pragma unroll
                for (int fn = 0; fn < 4; fn++) {
                    mma16816(acc[fm][fn], ah[fm], bh[fn]);
                    mma16816(acc[fm][fn], ah[fm], bl[fn]);
                    mma16816(acc[fm][fn], al[fm], bh[fn]);
                }
        }
        __syncthreads();
    }

    const int rbase = bm * 128 + warp_m * 64 + (lane >> 2);
    const int cbase = bn * 128 + warp_n * 32 + ((lane & 3) << 1);
#pragma unroll
    for (int fm = 0; fm < 4; fm++) {
        const int row = rbase + fm * 16;
#pragma unroll
        for (int fn = 0; fn < 4; fn++) {
            const int col = cbase + fn * 8;
            *(float2*)(C + (size_t)row * N + col) =
                make_float2(acc[fm][fn][0], acc[fm][fn][1]);
            *(float2*)(C + (size_t)(row + 8) * N + col) =
                make_float2(acc[fm][fn][2], acc[fm][fn][3]);
        }
    }
}

// ---------------------------------------------------------------------------
// Fused per-head RMSNorm + RoPE, in place.
// ---------------------------------------------------------------------------
__global__ __launch_bounds__(128)
void norm_rope_kernel(float* __restrict__ x, const float* __restrict__ w,
                      const float* __restrict__ fc, const float* __restrict__ fs,
                      int nheads)
{
    const int s = blockIdx.x, hh = blockIdx.y, d = threadIdx.x;
    float* row = x + ((size_t)s * nheads + hh) * HD;
    float v = row[d];
    float p = v * v;
#pragma unroll
    for (int o = 16; o > 0; o >>= 1) p += __shfl_xor_sync(0xffffffffu, p, o);
    __shared__ float ws[4];
    __shared__ float sx[128];
    const int lane = d & 31, wid = d >> 5;
    if (lane == 0) ws[wid] = p;
    __syncthreads();
    const float tot = ws[0] + ws[1] + ws[2] + ws[3];
    const float r = rsqrtf(tot * (1.0f / 128.0f) + 1e-6f);
    sx[d] = v * r * w[d];
    __syncthreads();
    const float c  = fc[s * 64 + (d & 63)];
    const float sn = fs[s * 64 + (d & 63)];
    float out;
    if (d < 64) out = sx[d] * c - sx[d + 64] * sn;
    else        out = sx[d - 64] * sn + sx[d] * c;
    row[d] = out;
}

__global__ void kvnew_kernel(const float* __restrict__ k, const float* __restrict__ v,
                             float* __restrict__ out)
{
    const int i = blockIdx.x * 256 + threadIdx.x;
    if (i < NKH * HD) {
        out[Y_SIZE + i]            = k[(size_t)(S_LEN - 1) * NKH * HD + i];
        out[Y_SIZE + NKH * HD + i] = v[(size_t)(S_LEN - 1) * NKH * HD + i];
    }
}

// ---------------------------------------------------------------------------
// HMMA causal flash attention. BM=64 (4 warps x 16 rows), BN=64, D=128.
// Scores: Qh*Kh + Qh*Kl + Ql*Kh. PV: Ph*Vh + Ph*Vl + Pl*Vh. fp32 softmax/O.
// Smem (bf16): Qh,Ql,Kh,Kl [64][QSTR] + Vth,Vtl [128][VSTR].
// ---------------------------------------------------------------------------
#define QSTR 136
#define VSTR 72
#define FH_SMEM ((4 * 64 * QSTR + 2 * 128 * VSTR) * 2)

__global__ __launch_bounds__(128)
void flash_mma(const bf16* __restrict__ Qh, const bf16* __restrict__ Ql,
               const bf16* __restrict__ Kh, const bf16* __restrict__ Kl,
               const bf16* __restrict__ Vth, const bf16* __restrict__ Vtl,
               float* __restrict__ O)
{
    extern __shared__ bf16 smx[];
    bf16* sQh = smx;
    bf16* sQl = smx + 64 * QSTR;
    bf16* sKh = smx + 2 * 64 * QSTR;
    bf16* sKl = smx + 3 * 64 * QSTR;
    bf16* sVh = smx + 4 * 64 * QSTR;
    bf16* sVl = sVh + 128 * VSTR;

    const int qt = (gridDim.x - 1) - blockIdx.x;   // long tiles first
    const int h = blockIdx.y;
    const int khead = h >> 1;
    const int qbase = qt * 64;
    const int tid = threadIdx.x;
    const int wid = tid >> 5, lane = tid & 31;
    const int m0 = wid * 16;

    const uint32_t baQh = smem_u32(sQh), baQl = smem_u32(sQl);
    const uint32_t baKh = smem_u32(sKh), baKl = smem_u32(sKl);
    const uint32_t baVh = smem_u32(sVh), baVl = smem_u32(sVl);

    const int a_row = lane & 15, a_kh = (lane >> 4) << 3;
    const int b_row = (lane & 7) + ((lane >> 4) << 3), b_kh = ((lane >> 3) & 1) << 3;

    // load Q tile once: [64 rows][128 d]
#pragma unroll
    for (int i = 0; i < 8; i++) {
        const int u = tid + (i << 7);
        const int row = u >> 4, c8 = (u & 15) << 3;
        const size_t g = ((size_t)(qbase + row) * NH + h) * HD + c8;
        const int so = row * QSTR + c8;
        *(uint4*)(sQh + so) = *(const uint4*)(Qh + g);
        *(uint4*)(sQl + so) = *(const uint4*)(Ql + g);
    }

    float oacc[16][4];
#pragma unroll
    for (int i = 0; i < 16; i++)
#pragma unroll
        for (int r = 0; r < 4; r++) oacc[i][r] = 0.f;
    float mrow0 = -1e30f, mrow1 = -1e30f, lrow0 = 0.f, lrow1 = 0.f;

    const int r0 = lane >> 2;          // local row in warp's 16
    const int cq = (lane & 3) << 1;    // quad col pair base

    for (int kt = 0; kt <= qt; kt++) {
        const int kbase = kt * 64;
        __syncthreads();
        // load K [64][128] and Vt [128][64]
#pragma unroll
        for (int i = 0; i < 8; i++) {
            const int u = tid + (i << 7);
            {
                const int row = u >> 4, c8 = (u & 15) << 3;
                const size_t g = ((size_t)(kbase + row) * NKH + khead) * HD + c8;
                const int so = row * QSTR + c8;
                *(uint4*)(sKh + so) = *(const uint4*)(Kh + g);
                *(uint4*)(sKl + so) = *(const uint4*)(Kl + g);
            }
            {
                const int row = u >> 3, c8 = (u & 7) << 3;
                const size_t g = ((size_t)khead * HD + row) * S_LEN + kbase + c8;
                const int so = row * VSTR + c8;
                *(uint4*)(sVh + so) = *(const uint4*)(Vth + g);
                *(uint4*)(sVl + so) = *(const uint4*)(Vtl + g);
            }
        }
        __syncthreads();

        // ---- scores ----
        float sacc[8][4];
#pragma unroll
        for (int f = 0; f < 8; f++)
#pragma unroll
            for (int r = 0; r < 4; r++) sacc[f][r] = 0.f;

#pragma unroll
        for (int kf = 0; kf < 8; kf++) {
            const int kk = kf << 4;
            uint32_t ah[4], al[4];
            ldsm4(ah, baQh + ((m0 + a_row) * QSTR + kk + a_kh) * 2);
            ldsm4(al, baQl + ((m0 + a_row) * QSTR + kk + a_kh) * 2);
#pragma unroll
            for (int fp = 0; fp < 4; fp++) {
                const uint32_t off = ((fp * 16 + b_row) * QSTR + kk + b_kh) * 2;
                uint32_t th[4], tl[4];
                ldsm4(th, baKh + off);
                ldsm4(tl, baKl + off);
                uint32_t bh0[2] = {th[0], th[1]}, bh1[2] = {th[2], th[3]};
                uint32_t bl0[2] = {tl[0], tl[1]}, bl1[2] = {tl[2], tl[3]};
                mma16816(sacc[2*fp],   ah, bh0);
                mma16816(sacc[2*fp],   ah, bl0);
                mma16816(sacc[2*fp],   al, bh0);
                mma16816(sacc[2*fp+1], ah, bh1);
                mma16816(sacc[2*fp+1], ah, bl1);
                mma16816(sacc[2*fp+1], al, bh1);
            }
        }

        // ---- softmax ----
#pragma unroll
        for (int f = 0; f < 8; f++)
#pragma unroll
            for (int r = 0; r < 4; r++) sacc[f][r] *= SCALE;

        if (kt == qt) {   // diagonal tile: causal mask
#pragma unroll
            for (int f = 0; f < 8; f++) {
                const int col = (f << 3) + cq;
                const int row0g = m0 + r0, row1g = m0 + r0 + 8;
                if (col     > row0g) sacc[f][0] = -1e9f;
                if (col + 1 > row0g) sacc[f][1] = -1e9f;
                if (col     > row1g) sacc[f][2] = -1e9f;
                if (col + 1 > row1g) sacc[f][3] = -1e9f;
            }
        }

        float tm0 = -1e30f, tm1 = -1e30f;
#pragma unroll
        for (int f = 0; f < 8; f++) {
            tm0 = fmaxf(tm0, fmaxf(sacc[f][0], sacc[f][1]));
            tm1 = fmaxf(tm1, fmaxf(sacc[f][2], sacc[f][3]));
        }
        tm0 = fmaxf(tm0, __shfl_xor_sync(0xffffffffu, tm0, 1));
        tm0 = fmaxf(tm0, __shfl_xor_sync(0xffffffffu, tm0, 2));
        tm1 = fmaxf(tm1, __shfl_xor_sync(0xffffffffu, tm1, 1));
        tm1 = fmaxf(tm1, __shfl_xor_sync(0xffffffffu, tm1, 2));

        const float mn0 = fmaxf(mrow0, tm0), mn1 = fmaxf(mrow1, tm1);
        const float cr0 = __expf(mrow0 - mn0), cr1 = __expf(mrow1 - mn1);
        float rs0 = 0.f, rs1 = 0.f;
#pragma unroll
        for (int f = 0; f < 8; f++) {
            sacc[f][0] = __expf(sacc[f][0] - mn0);
            sacc[f][1] = __expf(sacc[f][1] - mn0);
            sacc[f][2] = __expf(sacc[f][2] - mn1);
            sacc[f][3] = __expf(sacc[f][3] - mn1);
            rs0 += sacc[f][0] + sacc[f][1];
            rs1 += sacc[f][2] + sacc[f][3];
        }
        rs0 += __shfl_xor_sync(0xffffffffu, rs0, 1);
        rs0 += __shfl_xor_sync(0xffffffffu, rs0, 2);
        rs1 += __shfl_xor_sync(0xffffffffu, rs1, 1);
        rs1 += __shfl_xor_sync(0xffffffffu, rs1, 2);
        lrow0 = lrow0 * cr0 + rs0;
        lrow1 = lrow1 * cr1 + rs1;
        mrow0 = mn0; mrow1 = mn1;
#pragma unroll
        for (int i = 0; i < 16; i++) {
            oacc[i][0] *= cr0; oacc[i][1] *= cr0;
            oacc[i][2] *= cr1; oacc[i][3] *= cr1;
        }

        // ---- repack P (scores regs -> A frags, hi/lo split) ----
        uint32_t ph[4][4], pl[4][4];
#pragma unroll
        for (int t = 0; t < 4; t++) {
            split2(sacc[2*t][0],   sacc[2*t][1],   ph[t][0], pl[t][0]);
            split2(sacc[2*t][2],   sacc[2*t][3],   ph[t][1], pl[t][1]);
            split2(sacc[2*t+1][0], sacc[2*t+1][1], ph[t][2], pl[t][2]);
            split2(sacc[2*t+1][2], sacc[2*t+1][3], ph[t][3], pl[t][3]);
        }

        // ---- O += P @ V ----
#pragma unroll
        for (int dp = 0; dp < 8; dp++) {
#pragma unroll
            for (int t = 0; t < 4; t++) {
                const uint32_t off = ((dp * 16 + b_row) * VSTR + t * 16 + b_kh) * 2;
                uint32_t th[4], tl[4];
                ldsm4(th, baVh + off);
                ldsm4(tl, baVl + off);
                uint32_t bh0[2] = {th[0], th[1]}, bh1[2] = {th[2], th[3]};
                uint32_t bl0[2] = {tl[0], tl[1]}, bl1[2] = {tl[2], tl[3]};
                mma16816(oacc[2*dp],   ph[t], bh0);
                mma16816(oacc[2*dp],   ph[t], bl0);
                mma16816(oacc[2*dp],   pl[t], bh0);
                mma16816(oacc[2*dp+1], ph[t], bh1);
                mma16816(oacc[2*dp+1], ph[t], bl1);
                mma16816(oacc[2*dp+1], pl[t], bh1);
            }
        }
    }

    // epilogue
    const float inv0 = 1.0f / lrow0, inv1 = 1.0f / lrow1;
    const int gr0 = qbase + m0 + r0, gr1 = gr0 + 8;
#pragma unroll
    for (int nf = 0; nf < 16; nf++) {
        const int col = (nf << 3) + cq;
        *(float2*)(O + ((size_t)gr0 * NH + h) * HD + col) =
            make_float2(oacc[nf][0] * inv0, oacc[nf][1] * inv0);
        *(float2*)(O + ((size_t)gr1 * NH + h) * HD + col) =
            make_float2(oacc[nf][2] * inv1, oacc[nf][3] * inv1);
    }
}

// ---------------------------------------------------------------------------
extern "C" void kernel_launch(void* const* d_in, const int* in_sizes, int n_in,
                              void* d_out, int out_size)
{
    const float* X  = (const float*)d_in[0];
    const float* fc = (const float*)d_in[1];
    const float* fs = (const float*)d_in[2];
    // d_in[3] atten_mask unused: exactly causal, applied analytically
    const float* Wq = (const float*)d_in[4];
    const float* Wk = (const float*)d_in[5];
    const float* Wv = (const float*)d_in[6];
    const float* Wo = (const float*)d_in[7];
    const float* qw = (const float*)d_in[8];
    const float* kw = (const float*)d_in[9];
    float* out = (float*)d_out;

    float *q, *k, *v, *attn;
    bf16 *bf, *bf2;
    cudaGetSymbolAddress((void**)&q, g_q);
    cudaGetSymbolAddress((void**)&k, g_k);
    cudaGetSymbolAddress((void**)&v, g_v);
    cudaGetSymbolAddress((void**)&attn, g_attn);
    cudaGetSymbolAddress((void**)&bf, g_bf);
    cudaGetSymbolAddress((void**)&bf2, g_bf2);

    cudaFuncSetAttribute(mma_gemm, cudaFuncAttributeMaxDynamicSharedMemorySize,
                         MG_SMEM);
    cudaFuncSetAttribute(flash_mma, cudaFuncAttributeMaxDynamicSharedMemorySize,
                         FH_SMEM);

    // fp32 -> bf16 hi/lo splits for projections
    const int NB = 4194304, NS = 2097152;
    split_bf16<<<NB / 256, 256>>>(X,  bf + OFF_XH,  bf + OFF_XL,  NB);
    split_bf16<<<NB / 256, 256>>>(Wq, bf + OFF_WQH, bf + OFF_WQL, NB);
    split_bf16<<<NS / 256, 256>>>(Wk, bf + OFF_WKH, bf + OFF_WKL, NS);
    split_bf16<<<NS / 256, 256>>>(Wv, bf + OFF_WVH, bf + OFF_WVL, NS);
    split_bf16<<<NB / 256, 256>>>(Wo, bf + OFF_WOH, bf + OFF_WOL, NB);

    // QKV projections (HMMA, 3-term bf16 split)
    mma_gemm<<<dim3(16, 16), 256, MG_SMEM>>>(bf + OFF_XH, bf + OFF_XL,
                                             bf + OFF_WQH, bf + OFF_WQL,
                                             q, S_LEN, NH * HD, HID);
    mma_gemm<<<dim3(8, 16), 256, MG_SMEM>>>(bf + OFF_XH, bf + OFF_XL,
                                            bf + OFF_WKH, bf + OFF_WKL,
                                            k, S_LEN, NKH * HD, HID);
    mma_gemm<<<dim3(8, 16), 256, MG_SMEM>>>(bf + OFF_XH, bf + OFF_XL,
                                            bf + OFF_WVH, bf + OFF_WVL,
                                            v, S_LEN, NKH * HD, HID);

    // per-head RMSNorm + RoPE (in place, fp32)
    norm_rope_kernel<<<dim3(S_LEN, NH),  128>>>(q, qw, fc, fs, NH);
    norm_rope_kernel<<<dim3(S_LEN, NKH), 128>>>(k, kw, fc, fs, NKH);

    // k_new / v_new tail outputs (fp32 sources)
    kvnew_kernel<<<4, 256>>>(k, v, out);

    // flash operand splits
    split_bf16<<<NB / 256, 256>>>(q, bf2 + OFF_QH, bf2 + OFF_QL, NB);
    split_bf16<<<NS / 256, 256>>>(k, bf2 + OFF_KH, bf2 + OFF_KL, NS);
    vtrans_split<<<dim3(64, 4, 8), dim3(32, 8)>>>(v, bf2 + OFF_VTH, bf2 + OFF_VTL);

    // HMMA causal flash attention
    flash_mma<<<dim3(S_LEN / 64, NH), 128, FH_SMEM>>>(
        bf2 + OFF_QH, bf2 + OFF_QL, bf2 + OFF_KH, bf2 + OFF_KL,
        bf2 + OFF_VTH, bf2 + OFF_VTL, attn);

    // output projection directly into d_out
    split_bf16<<<NB / 256, 256>>>(attn, bf + OFF_ATH, bf + OFF_ATL, NB);
    mma_gemm<<<dim3(16, 16), 256, MG_SMEM>>>(bf + OFF_ATH, bf + OFF_ATL,
                                             bf + OFF_WOH, bf + OFF_WOL,
                                             out, S_LEN, HID, NH * HD);
}

// round 13
// speedup vs baseline: 3.1156x; 1.0574x over previous
#include <cuda_runtime.h>
#include <cuda_bf16.h>
#include <cstdint>

typedef __nv_bfloat16 bf16;

#define S_LEN 2048
#define HID   2048
#define NH    16
#define NKH   8
#define HD    128
#define SCALE 0.08838834764831845f
#define Y_SIZE (S_LEN * NH * HD)

// ---------------- fp32 scratch ----------------
__device__ float g_q[S_LEN * NH * HD];     // 16 MB
__device__ float g_k[S_LEN * NKH * HD];    //  8 MB
__device__ float g_v[S_LEN * NKH * HD];    //  8 MB

// ---------------- bf16 split arena #1 (gemm operands) ----------------
#define OFF_XH   0u
#define OFF_XL   4194304u
#define OFF_WQH  8388608u
#define OFF_WQL  12582912u
#define OFF_WKH  16777216u
#define OFF_WKL  18874368u
#define OFF_WVH  20971520u
#define OFF_WVL  23068672u
#define OFF_WOH  25165824u
#define OFF_WOL  29360128u
#define OFF_ATH  33554432u
#define OFF_ATL  37748736u
__device__ __align__(1024) bf16 g_bf[41943040];

// ---------------- bf16 split arena #2 (flash operands) ----------------
#define OFF_QH   0u
#define OFF_QL   4194304u
#define OFF_KH   8388608u
#define OFF_KL   10485760u
#define OFF_VTH  12582912u        // [kh][d][s] transposed
#define OFF_VTL  14680064u
__device__ __align__(1024) bf16 g_bf2[16777216];

__device__ __forceinline__ uint32_t smem_u32(const void* p) {
    uint32_t a;
    asm("{ .reg .u64 t; cvta.to.shared.u64 t, %1; cvt.u32.u64 %0, t; }"
        : "=r"(a) : "l"(p));
    return a;
}
__device__ __forceinline__ void ldsm4(uint32_t* r, uint32_t addr) {
    asm volatile("ldmatrix.sync.aligned.m8n8.x4.shared.b16 {%0,%1,%2,%3}, [%4];"
                 : "=r"(r[0]), "=r"(r[1]), "=r"(r[2]), "=r"(r[3]) : "r"(addr));
}
__device__ __forceinline__ void mma16816(float* c, const uint32_t* a, const uint32_t* b) {
    asm volatile("mma.sync.aligned.m16n8k16.row.col.f32.bf16.bf16.f32 "
                 "{%0,%1,%2,%3}, {%4,%5,%6,%7}, {%8,%9}, {%0,%1,%2,%3};"
                 : "+f"(c[0]), "+f"(c[1]), "+f"(c[2]), "+f"(c[3])
                 : "r"(a[0]), "r"(a[1]), "r"(a[2]), "r"(a[3]), "r"(b[0]), "r"(b[1]));
}
__device__ __forceinline__ void cpa16(uint32_t s, const void* g) {
    asm volatile("cp.async.cg.shared.global [%0], [%1], 16;" :: "r"(s), "l"(g));
}
// pack two floats into bf16x2 hi + bf16x2 lo
__device__ __forceinline__ void split2(float a, float b, uint32_t& h, uint32_t& l) {
    bf16 ha = __float2bfloat16(a), hb = __float2bfloat16(b);
    float la = a - __bfloat162float(ha), lb = b - __bfloat162float(hb);
    __nv_bfloat162 hv(ha, hb);
    __nv_bfloat162 lv = __floats2bfloat162_rn(la, lb);
    h = *(uint32_t*)&hv;
    l = *(uint32_t*)&lv;
}

// ---------------------------------------------------------------------------
// one launch: split X, Wq, Wk, Wv, Wo  (all sizes multiple of 256)
// ---------------------------------------------------------------------------
__global__ __launch_bounds__(256)
void split5(const float* __restrict__ X,  const float* __restrict__ Wq,
            const float* __restrict__ Wk, const float* __restrict__ Wv,
            const float* __restrict__ Wo, bf16* __restrict__ bf)
{
    const int b = blockIdx.x;
    const float* src;
    bf16 *h, *l;
    int base;
    if (b < 16384)      { src = X;  h = bf + OFF_XH;  l = bf + OFF_XL;  base = b; }
    else if (b < 32768) { src = Wq; h = bf + OFF_WQH; l = bf + OFF_WQL; base = b - 16384; }
    else if (b < 40960) { src = Wk; h = bf + OFF_WKH; l = bf + OFF_WKL; base = b - 32768; }
    else if (b < 49152) { src = Wv; h = bf + OFF_WVH; l = bf + OFF_WVL; base = b - 40960; }
    else                { src = Wo; h = bf + OFF_WOH; l = bf + OFF_WOL; base = b - 49152; }
    const int i = base * 256 + threadIdx.x;
    float v = src[i];
    bf16 hh = __float2bfloat16(v);
    h[i] = hh;
    l[i] = __float2bfloat16(v - __bfloat162float(hh));
}

// ---------------------------------------------------------------------------
// V transpose + split: g_v [s][kh][128] fp32 -> vt [kh][128][2048] bf16 hi/lo
// ---------------------------------------------------------------------------
__global__ __launch_bounds__(256)
void vtrans_split(const float* __restrict__ v, bf16* __restrict__ vh,
                  bf16* __restrict__ vl)
{
    __shared__ float t[32][33];
    const int s0 = blockIdx.x * 32, d0 = blockIdx.y * 32, kh = blockIdx.z;
#pragma unroll
    for (int i = 0; i < 4; i++) {
        const int row = s0 + threadIdx.y + i * 8;
        t[threadIdx.y + i * 8][threadIdx.x] =
            v[((size_t)row * NKH + kh) * HD + d0 + threadIdx.x];
    }
    __syncthreads();
#pragma unroll
    for (int i = 0; i < 4; i++) {
        const int d = d0 + threadIdx.y + i * 8;
        const int s = s0 + threadIdx.x;
        float val = t[threadIdx.x][threadIdx.y + i * 8];
        bf16 h = __float2bfloat16(val);
        const size_t o = ((size_t)kh * HD + d) * S_LEN + s;
        vh[o] = h;
        vl[o] = __float2bfloat16(val - __bfloat162float(h));
    }
}

// ---------------------------------------------------------------------------
// cp.async double-buffered HMMA GEMM mainloop (shared by qkv_gemm / mma_gemm2)
// 128x128 CTA tile, K-chunk 32, 2 stages. Tiles [128][GST2] bf16 per array.
// ---------------------------------------------------------------------------
#define GST2 40
#define G2_ARR   (128 * GST2 * 2)          // bytes per array per stage (10240)
#define G2_STAGE (4 * G2_ARR)              // 40960
#define MG2_SMEM (2 * G2_STAGE)            // 81920

__device__ __forceinline__ void g2_load(uint32_t st, const bf16* gAh,
                                        const bf16* gAl, const bf16* gBh,
                                        const bf16* gBl, int K, int k0, int tid)
{
#pragma unroll
    for (int t = 0; t < 2; t++) {
        const int u = tid + (t << 8);
        const int row = u >> 2, grp = (u & 3) << 3;
        const uint32_t so = st + row * (GST2 * 2) + grp * 2;
        const size_t go = (size_t)row * K + k0 + grp;
        cpa16(so,              gAh + go);
        cpa16(so + G2_ARR,     gAl + go);
        cpa16(so + 2 * G2_ARR, gBh + go);
        cpa16(so + 3 * G2_ARR, gBl + go);
    }
    asm volatile("cp.async.commit_group;" ::: "memory");
}

__device__ __forceinline__ void g2_mainloop(
    const bf16* gAh, const bf16* gAl, const bf16* gBh, const bf16* gBl,
    int K, uint32_t sb, int tid, int warp_m, int warp_n, int lane,
    float acc[4][4][4])
{
    const int a_row = lane & 15, a_kh = (lane >> 4) << 3;
    const int b_row = (lane & 7) + ((lane >> 4) << 3), b_kh = ((lane >> 3) & 1) << 3;
    const int NC = K >> 5;

    g2_load(sb, gAh, gAl, gBh, gBl, K, 0, tid);

    for (int c = 0; c < NC; c++) {
        if (c + 1 < NC) {
            g2_load(sb + ((c + 1) & 1) * G2_STAGE, gAh, gAl, gBh, gBl, K,
                    (c + 1) << 5, tid);
            asm volatile("cp.async.wait_group 1;" ::: "memory");
        } else {
            asm volatile("cp.async.wait_group 0;" ::: "memory");
        }
        __syncthreads();
        const uint32_t st = sb + (c & 1) * G2_STAGE;
#pragma unroll
        for (int ks = 0; ks < 2; ks++) {
            const int kk = ks << 4;
            uint32_t ah[4][4], al[4][4], bh[4][2], bl[4][2];
#pragma unroll
            for (int fm = 0; fm < 4; fm++) {
                const uint32_t off =
                    st + ((warp_m * 64 + fm * 16 + a_row) * GST2 + kk + a_kh) * 2;
                ldsm4(ah[fm], off);
                ldsm4(al[fm], off + G2_ARR);
            }
#pragma unroll
            for (int fp = 0; fp < 2; fp++) {
                const uint32_t off =
                    st + ((warp_n * 32 + fp * 16 + b_row) * GST2 + kk + b_kh) * 2;
                uint32_t t[4];
                ldsm4(t, off + 2 * G2_ARR);
                bh[2*fp][0] = t[0]; bh[2*fp][1] = t[1];
                bh[2*fp+1][0] = t[2]; bh[2*fp+1][1] = t[3];
                ldsm4(t, off + 3 * G2_ARR);
                bl[2*fp][0] = t[0]; bl[2*fp][1] = t[1];
                bl[2*fp+1][0] = t[2]; bl[2*fp+1][1] = t[3];
            }
#pragma unroll
            for (int fm = 0; fm < 4; fm++)
#pragma unroll
                for (int fn = 0; fn < 4; fn++) {
                    mma16816(acc[fm][fn], ah[fm], bh[fn]);
                    mma16816(acc[fm][fn], ah[fm], bl[fn]);
                    mma16816(acc[fm][fn], al[fm], bh[fn]);
                }
        }
        __syncthreads();
    }
}

__device__ __forceinline__ void g2_epilogue(float* C, int Nout, int rbase0,
                                            int cbase0, int warp_m, int warp_n,
                                            int lane, float acc[4][4][4])
{
    const int rbase = rbase0 + warp_m * 64 + (lane >> 2);
    const int cbase = cbase0 + warp_n * 32 + ((lane & 3) << 1);
#pragma unroll
    for (int fm = 0; fm < 4; fm++) {
        const int row = rbase + fm * 16;
#pragma unroll
        for (int fn = 0; fn < 4; fn++) {
            const int col = cbase + fn * 8;
            *(float2*)(C + (size_t)row * Nout + col) =
                make_float2(acc[fm][fn][0], acc[fm][fn][1]);
            *(float2*)(C + (size_t)(row + 8) * Nout + col) =
                make_float2(acc[fm][fn][2], acc[fm][fn][3]);
        }
    }
}

// fused QKV projection: grid (32, 16). bn<16 -> Q, <24 -> K, else V.
__global__ __launch_bounds__(256)
void qkv_gemm(const bf16* __restrict__ bfarena, float* __restrict__ q,
              float* __restrict__ k, float* __restrict__ v)
{
    extern __shared__ char smc[];
    const uint32_t sb = smem_u32(smc);
    const int tid = threadIdx.x, wid = tid >> 5, lane = tid & 31;
    const int warp_m = wid >> 2, warp_n = wid & 3;
    const int bm = blockIdx.y, bn = blockIdx.x;

    const bf16* Xh = bfarena + OFF_XH;
    const bf16* Xl = bfarena + OFF_XL;
    const bf16 *Bh, *Bl;
    float* C;
    int Nout, cb;
    if (bn < 16)      { Bh = bfarena + OFF_WQH; Bl = bfarena + OFF_WQL;
                        C = q; Nout = 2048; cb = bn * 128; }
    else if (bn < 24) { Bh = bfarena + OFF_WKH; Bl = bfarena + OFF_WKL;
                        C = k; Nout = 1024; cb = (bn - 16) * 128; }
    else              { Bh = bfarena + OFF_WVH; Bl = bfarena + OFF_WVL;
                        C = v; Nout = 1024; cb = (bn - 24) * 128; }

    float acc[4][4][4];
#pragma unroll
    for (int i = 0; i < 4; i++)
#pragma unroll
        for (int j = 0; j < 4; j++)
#pragma unroll
            for (int r = 0; r < 4; r++) acc[i][j][r] = 0.f;

    g2_mainloop(Xh + (size_t)bm * 128 * HID, Xl + (size_t)bm * 128 * HID,
                Bh + (size_t)cb * HID, Bl + (size_t)cb * HID,
                HID, sb, tid, warp_m, warp_n, lane, acc);
    g2_epilogue(C, Nout, bm * 128, cb, warp_m, warp_n, lane, acc);
}

// generic NT gemm (used for Wo)
__global__ __launch_bounds__(256)
void mma_gemm2(const bf16* __restrict__ Ahi, const bf16* __restrict__ Alo,
               const bf16* __restrict__ Bhi, const bf16* __restrict__ Blo,
               float* __restrict__ C, int N, int K)
{
    extern __shared__ char smc[];
    const uint32_t sb = smem_u32(smc);
    const int tid = threadIdx.x, wid = tid >> 5, lane = tid & 31;
    const int warp_m = wid >> 2, warp_n = wid & 3;
    const int bm = blockIdx.y, bn = blockIdx.x;

    float acc[4][4][4];
#pragma unroll
    for (int i = 0; i < 4; i++)
#pragma unroll
        for (int j = 0; j < 4; j++)
#pragma unroll
            for (int r = 0; r < 4; r++) acc[i][j][r] = 0.f;

    g2_mainloop(Ahi + (size_t)bm * 128 * K, Alo + (size_t)bm * 128 * K,
                Bhi + (size_t)bn * 128 * K, Blo + (size_t)bn * 128 * K,
                K, sb, tid, warp_m, warp_n, lane, acc);
    g2_epilogue(C, N, bm * 128, bn * 128, warp_m, warp_n, lane, acc);
}

// ---------------------------------------------------------------------------
// Fused per-head RMSNorm + RoPE -> bf16 hi/lo split output.
// ---------------------------------------------------------------------------
__global__ __launch_bounds__(128)
void norm_rope_split(const float* __restrict__ x, const float* __restrict__ w,
                     const float* __restrict__ fc, const float* __restrict__ fs,
                     bf16* __restrict__ oh, bf16* __restrict__ ol, int nheads)
{
    const int s = blockIdx.x, hh = blockIdx.y, d = threadIdx.x;
    const float* row = x + ((size_t)s * nheads + hh) * HD;
    float v = row[d];
    float p = v * v;
#pragma unroll
    for (int o = 16; o > 0; o >>= 1) p += __shfl_xor_sync(0xffffffffu, p, o);
    __shared__ float ws[4];
    __shared__ float sx[128];
    const int lane = d & 31, wid = d >> 5;
    if (lane == 0) ws[wid] = p;
    __syncthreads();
    const float tot = ws[0] + ws[1] + ws[2] + ws[3];
    const float r = rsqrtf(tot * (1.0f / 128.0f) + 1e-6f);
    sx[d] = v * r * w[d];
    __syncthreads();
    const float c  = fc[s * 64 + (d & 63)];
    const float sn = fs[s * 64 + (d & 63)];
    float out;
    if (d < 64) out = sx[d] * c - sx[d + 64] * sn;
    else        out = sx[d - 64] * sn + sx[d] * c;
    const size_t o = ((size_t)s * nheads + hh) * HD + d;
    bf16 h = __float2bfloat16(out);
    oh[o] = h;
    ol[o] = __float2bfloat16(out - __bfloat162float(h));
}

// k_new (post-RoPE k reconstructed hi+lo), v_new (raw v fp32)
__global__ void kvnew_kernel(const bf16* __restrict__ kh, const bf16* __restrict__ kl,
                             const float* __restrict__ v, float* __restrict__ out)
{
    const int i = blockIdx.x * 256 + threadIdx.x;
    if (i < NKH * HD) {
        const size_t o = (size_t)(S_LEN - 1) * NKH * HD + i;
        out[Y_SIZE + i] = __bfloat162float(kh[o]) + __bfloat162float(kl[o]);
        out[Y_SIZE + NKH * HD + i] = v[o];
    }
}

// ---------------------------------------------------------------------------
// HMMA causal flash attention. BM=64 (4 warps x 16 rows), BN=64, D=128.
// Epilogue writes bf16 hi/lo attn directly (fused split).
// ---------------------------------------------------------------------------
#define QSTR 136
#define VSTR 72
#define FH_SMEM ((4 * 64 * QSTR + 2 * 128 * VSTR) * 2)

__global__ __launch_bounds__(128)
void flash_mma(const bf16* __restrict__ Qh, const bf16* __restrict__ Ql,
               const bf16* __restrict__ Kh, const bf16* __restrict__ Kl,
               const bf16* __restrict__ Vth, const bf16* __restrict__ Vtl,
               bf16* __restrict__ Oh, bf16* __restrict__ Ol)
{
    extern __shared__ bf16 smx[];
    bf16* sQh = smx;
    bf16* sQl = smx + 64 * QSTR;
    bf16* sKh = smx + 2 * 64 * QSTR;
    bf16* sKl = smx + 3 * 64 * QSTR;
    bf16* sVh = smx + 4 * 64 * QSTR;
    bf16* sVl = sVh + 128 * VSTR;

    const int qt = (gridDim.x - 1) - blockIdx.x;
    const int h = blockIdx.y;
    const int khead = h >> 1;
    const int qbase = qt * 64;
    const int tid = threadIdx.x;
    const int wid = tid >> 5, lane = tid & 31;
    const int m0 = wid * 16;

    const uint32_t baQh = smem_u32(sQh), baQl = smem_u32(sQl);
    const uint32_t baKh = smem_u32(sKh), baKl = smem_u32(sKl);
    const uint32_t baVh = smem_u32(sVh), baVl = smem_u32(sVl);

    const int a_row = lane & 15, a_kh = (lane >> 4) << 3;
    const int b_row = (lane & 7) + ((lane >> 4) << 3), b_kh = ((lane >> 3) & 1) << 3;

#pragma unroll
    for (int i = 0; i < 8; i++) {
        const int u = tid + (i << 7);
        const int row = u >> 4, c8 = (u & 15) << 3;
        const size_t g = ((size_t)(qbase + row) * NH + h) * HD + c8;
        const int so = row * QSTR + c8;
        *(uint4*)(sQh + so) = *(const uint4*)(Qh + g);
        *(uint4*)(sQl + so) = *(const uint4*)(Ql + g);
    }

    float oacc[16][4];
#pragma unroll
    for (int i = 0; i < 16; i++)
#pragma unroll
        for (int r = 0; r < 4; r++) oacc[i][r] = 0.f;
    float mrow0 = -1e30f, mrow1 = -1e30f, lrow0 = 0.f, lrow1 = 0.f;

    const int r0 = lane >> 2;
    const int cq = (lane & 3) << 1;

    for (int kt = 0; kt <= qt; kt++) {
        const int kbase = kt * 64;
        __syncthreads();
#pragma unroll
        for (int i = 0; i < 8; i++) {
            const int u = tid + (i << 7);
            {
                const int row = u >> 4, c8 = (u & 15) << 3;
                const size_t g = ((size_t)(kbase + row) * NKH + khead) * HD + c8;
                const int so = row * QSTR + c8;
                *(uint4*)(sKh + so) = *(const uint4*)(Kh + g);
                *(uint4*)(sKl + so) = *(const uint4*)(Kl + g);
            }
            {
                const int row = u >> 3, c8 = (u & 7) << 3;
                const size_t g = ((size_t)khead * HD + row) * S_LEN + kbase + c8;
                const int so = row * VSTR + c8;
                *(uint4*)(sVh + so) = *(const uint4*)(Vth + g);
                *(uint4*)(sVl + so) = *(const uint4*)(Vtl + g);
            }
        }
        __syncthreads();

        float sacc[8][4];
#pragma unroll
        for (int f = 0; f < 8; f++)
#pragma unroll
            for (int r = 0; r < 4; r++) sacc[f][r] = 0.f;

#pragma unroll
        for (int kf = 0; kf < 8; kf++) {
            const int kk = kf << 4;
            uint32_t ah[4], al[4];
            ldsm4(ah, baQh + ((m0 + a_row) * QSTR + kk + a_kh) * 2);
            ldsm4(al, baQl + ((m0 + a_row) * QSTR + kk + a_kh) * 2);
#pragma unroll
            for (int fp = 0; fp < 4; fp++) {
                const uint32_t off = ((fp * 16 + b_row) * QSTR + kk + b_kh) * 2;
                uint32_t th[4], tl[4];
                ldsm4(th, baKh + off);
                ldsm4(tl, baKl + off);
                uint32_t bh0[2] = {th[0], th[1]}, bh1[2] = {th[2], th[3]};
                uint32_t bl0[2] = {tl[0], tl[1]}, bl1[2] = {tl[2], tl[3]};
                mma16816(sacc[2*fp],   ah, bh0);
                mma16816(sacc[2*fp],   ah, bl0);
                mma16816(sacc[2*fp],   al, bh0);
                mma16816(sacc[2*fp+1], ah, bh1);
                mma16816(sacc[2*fp+1], ah, bl1);
                mma16816(sacc[2*fp+1], al, bh1);
            }
        }

#pragma unroll
        for (int f = 0; f < 8; f++)
#pragma unroll
            for (int r = 0; r < 4; r++) sacc[f][r] *= SCALE;

        if (kt == qt) {
#pragma unroll
            for (int f = 0; f < 8; f++) {
                const int col = (f << 3) + cq;
                const int row0g = m0 + r0, row1g = m0 + r0 + 8;
                if (col     > row0g) sacc[f][0] = -1e9f;
                if (col + 1 > row0g) sacc[f][1] = -1e9f;
                if (col     > row1g) sacc[f][2] = -1e9f;
                if (col + 1 > row1g) sacc[f][3] = -1e9f;
            }
        }

        float tm0 = -1e30f, tm1 = -1e30f;
#pragma unroll
        for (int f = 0; f < 8; f++) {
            tm0 = fmaxf(tm0, fmaxf(sacc[f][0], sacc[f][1]));
            tm1 = fmaxf(tm1, fmaxf(sacc[f][2], sacc[f][3]));
        }
        tm0 = fmaxf(tm0, __shfl_xor_sync(0xffffffffu, tm0, 1));
        tm0 = fmaxf(tm0, __shfl_xor_sync(0xffffffffu, tm0, 2));
        tm1 = fmaxf(tm1, __shfl_xor_sync(0xffffffffu, tm1, 1));
        tm1 = fmaxf(tm1, __shfl_xor_sync(0xffffffffu, tm1, 2));

        const float mn0 = fmaxf(mrow0, tm0), mn1 = fmaxf(mrow1, tm1);
        const float cr0 = __expf(mrow0 - mn0), cr1 = __expf(mrow1 - mn1);
        float rs0 = 0.f, rs1 = 0.f;
#pragma unroll
        for (int f = 0; f < 8; f++) {
            sacc[f][0] = __expf(sacc[f][0] - mn0);
            sacc[f][1] = __expf(sacc[f][1] - mn0);
            sacc[f][2] = __expf(sacc[f][2] - mn1);
            sacc[f][3] = __expf(sacc[f][3] - mn1);
            rs0 += sacc[f][0] + sacc[f][1];
            rs1 += sacc[f][2] + sacc[f][3];
        }
        rs0 += __shfl_xor_sync(0xffffffffu, rs0, 1);
        rs0 += __shfl_xor_sync(0xffffffffu, rs0, 2);
        rs1 += __shfl_xor_sync(0xffffffffu, rs1, 1);
        rs1 += __shfl_xor_sync(0xffffffffu, rs1, 2);
        lrow0 = lrow0 * cr0 + rs0;
        lrow1 = lrow1 * cr1 + rs1;
        mrow0 = mn0; mrow1 = mn1;
#pragma unroll
        for (int i = 0; i < 16; i++) {
            oacc[i][0] *= cr0; oacc[i][1] *= cr0;
            oacc[i][2] *= cr1; oacc[i][3] *= cr1;
        }

        uint32_t ph[4][4], pl[4][4];
#pragma unroll
        for (int t = 0; t < 4; t++) {
            split2(sacc[2*t][0],   sacc[2*t][1],   ph[t][0], pl[t][0]);
            split2(sacc[2*t][2],   sacc[2*t][3],   ph[t][1], pl[t][1]);
            split2(sacc[2*t+1][0], sacc[2*t+1][1], ph[t][2], pl[t][2]);
            split2(sacc[2*t+1][2], sacc[2*t+1][3], ph[t][3], pl[t][3]);
        }

#pragma unroll
        for (int dp = 0; dp < 8; dp++) {
#pragma unroll
            for (int t = 0; t < 4; t++) {
                const uint32_t off = ((dp * 16 + b_row) * VSTR + t * 16 + b_kh) * 2;
                uint32_t th[4], tl[4];
                ldsm4(th, baVh + off);
                ldsm4(tl, baVl + off);
                uint32_t bh0[2] = {th[0], th[1]}, bh1[2] = {th[2], th[3]};
                uint32_t bl0[2] = {tl[0], tl[1]}, bl1[2] = {tl[2], tl[3]};
                mma16816(oacc[2*dp],   ph[t], bh0);
                mma16816(oacc[2*dp],   ph[t], bl0);
                mma16816(oacc[2*dp],   pl[t], bh0);
                mma16816(oacc[2*dp+1], ph[t], bh1);
                mma16816(oacc[2*dp+1], ph[t], bl1);
                mma16816(oacc[2*dp+1], pl[t], bh1);
            }
        }
    }

    // epilogue: normalize + fused bf16 hi/lo split directly into attn arena
    const float inv0 = 1.0f / lrow0, inv1 = 1.0f / lrow1;
    const int gr0 = qbase + m0 + r0, gr1 = gr0 + 8;
#pragma unroll
    for (int nf = 0; nf < 16; nf++) {
        const int col = (nf << 3) + cq;
        const size_t o0 = ((size_t)gr0 * NH + h) * HD + col;
        const size_t o1 = ((size_t)gr1 * NH + h) * HD + col;
        uint32_t hh, ll;
        split2(oacc[nf][0] * inv0, oacc[nf][1] * inv0, hh, ll);
        *(uint32_t*)(Oh + o0) = hh;
        *(uint32_t*)(Ol + o0) = ll;
        split2(oacc[nf][2] * inv1, oacc[nf][3] * inv1, hh, ll);
        *(uint32_t*)(Oh + o1) = hh;
        *(uint32_t*)(Ol + o1) = ll;
    }
}

// ---------------------------------------------------------------------------
extern "C" void kernel_launch(void* const* d_in, const int* in_sizes, int n_in,
                              void* d_out, int out_size)
{
    const float* X  = (const float*)d_in[0];
    const float* fc = (const float*)d_in[1];
    const float* fs = (const float*)d_in[2];
    // d_in[3] atten_mask unused: exactly causal, applied analytically
    const float* Wq = (const float*)d_in[4];
    const float* Wk = (const float*)d_in[5];
    const float* Wv = (const float*)d_in[6];
    const float* Wo = (const float*)d_in[7];
    const float* qw = (const float*)d_in[8];
    const float* kw = (const float*)d_in[9];
    float* out = (float*)d_out;

    float *q, *k, *v;
    bf16 *bf, *bf2;
    cudaGetSymbolAddress((void**)&q, g_q);
    cudaGetSymbolAddress((void**)&k, g_k);
    cudaGetSymbolAddress((void**)&v, g_v);
    cudaGetSymbolAddress((void**)&bf, g_bf);
    cudaGetSymbolAddress((void**)&bf2, g_bf2);

    cudaFuncSetAttribute(qkv_gemm, cudaFuncAttributeMaxDynamicSharedMemorySize,
                         MG2_SMEM);
    cudaFuncSetAttribute(mma_gemm2, cudaFuncAttributeMaxDynamicSharedMemorySize,
                         MG2_SMEM);
    cudaFuncSetAttribute(flash_mma, cudaFuncAttributeMaxDynamicSharedMemorySize,
                         FH_SMEM);

    // one launch: split X + all weights to bf16 hi/lo
    split5<<<65536, 256>>>(X, Wq, Wk, Wv, Wo, bf);

    // fused QKV projection (cp.async double-buffered HMMA)
    qkv_gemm<<<dim3(32, 16), 256, MG2_SMEM>>>(bf, q, k, v);

    // RMSNorm + RoPE fused with bf16 hi/lo split
    norm_rope_split<<<dim3(S_LEN, NH),  128>>>(q, qw, fc, fs,
                                               bf2 + OFF_QH, bf2 + OFF_QL, NH);
    norm_rope_split<<<dim3(S_LEN, NKH), 128>>>(k, kw, fc, fs,
                                               bf2 + OFF_KH, bf2 + OFF_KL, NKH);

    // k_new / v_new tail outputs
    kvnew_kernel<<<4, 256>>>(bf2 + OFF_KH, bf2 + OFF_KL, v, out);

    // V transpose + split
    vtrans_split<<<dim3(64, 4, 8), dim3(32, 8)>>>(v, bf2 + OFF_VTH, bf2 + OFF_VTL);

    // HMMA causal flash attention (epilogue writes bf16 hi/lo attn)
    flash_mma<<<dim3(S_LEN / 64, NH), 128, FH_SMEM>>>(
        bf2 + OFF_QH, bf2 + OFF_QL, bf2 + OFF_KH, bf2 + OFF_KL,
        bf2 + OFF_VTH, bf2 + OFF_VTL, bf + OFF_ATH, bf + OFF_ATL);

    // output projection directly into d_out
    mma_gemm2<<<dim3(16, 16), 256, MG2_SMEM>>>(bf + OFF_ATH, bf + OFF_ATL,
                                               bf + OFF_WOH, bf + OFF_WOL,
                                               out, HID, NH * HD);
}

// round 15
// speedup vs baseline: 3.1490x; 1.0107x over previous
#include <cuda_runtime.h>
#include <cuda_bf16.h>
#include <cstdint>

typedef __nv_bfloat16 bf16;

#define S_LEN 2048
#define HID   2048
#define NH    16
#define NKH   8
#define HD    128
#define SCALE 0.08838834764831845f
#define Y_SIZE (S_LEN * NH * HD)

// ---------------- fp32 scratch ----------------
__device__ float g_q[S_LEN * NH * HD];     // 16 MB
__device__ float g_k[S_LEN * NKH * HD];    //  8 MB
__device__ float g_v[S_LEN * NKH * HD];    //  8 MB

// ---------------- bf16 split arena #1 (gemm operands) ----------------
#define OFF_XH   0u
#define OFF_XL   4194304u
#define OFF_WQH  8388608u
#define OFF_WQL  12582912u
#define OFF_WKH  16777216u
#define OFF_WKL  18874368u
#define OFF_WVH  20971520u
#define OFF_WVL  23068672u
#define OFF_WOH  25165824u
#define OFF_WOL  29360128u
#define OFF_ATH  33554432u
#define OFF_ATL  37748736u
__device__ __align__(1024) bf16 g_bf[41943040];

// ---------------- bf16 split arena #2 (flash operands) ----------------
#define OFF_QH   0u
#define OFF_QL   4194304u
#define OFF_KH   8388608u
#define OFF_KL   10485760u
#define OFF_VTH  12582912u        // [kh][d][s] transposed
#define OFF_VTL  14680064u
__device__ __align__(1024) bf16 g_bf2[16777216];

__device__ __forceinline__ uint32_t smem_u32(const void* p) {
    uint32_t a;
    asm("{ .reg .u64 t; cvta.to.shared.u64 t, %1; cvt.u32.u64 %0, t; }"
        : "=r"(a) : "l"(p));
    return a;
}
__device__ __forceinline__ void ldsm4(uint32_t* r, uint32_t addr) {
    asm volatile("ldmatrix.sync.aligned.m8n8.x4.shared.b16 {%0,%1,%2,%3}, [%4];"
                 : "=r"(r[0]), "=r"(r[1]), "=r"(r[2]), "=r"(r[3]) : "r"(addr));
}
__device__ __forceinline__ void mma16816(float* c, const uint32_t* a, const uint32_t* b) {
    asm volatile("mma.sync.aligned.m16n8k16.row.col.f32.bf16.bf16.f32 "
                 "{%0,%1,%2,%3}, {%4,%5,%6,%7}, {%8,%9}, {%0,%1,%2,%3};"
                 : "+f"(c[0]), "+f"(c[1]), "+f"(c[2]), "+f"(c[3])
                 : "r"(a[0]), "r"(a[1]), "r"(a[2]), "r"(a[3]), "r"(b[0]), "r"(b[1]));
}
__device__ __forceinline__ void cpa16(uint32_t s, const void* g) {
    asm volatile("cp.async.cg.shared.global [%0], [%1], 16;" :: "r"(s), "l"(g));
}
__device__ __forceinline__ void split2(float a, float b, uint32_t& h, uint32_t& l) {
    bf16 ha = __float2bfloat16(a), hb = __float2bfloat16(b);
    float la = a - __bfloat162float(ha), lb = b - __bfloat162float(hb);
    __nv_bfloat162 hv(ha, hb);
    __nv_bfloat162 lv = __floats2bfloat162_rn(la, lb);
    h = *(uint32_t*)&hv;
    l = *(uint32_t*)&lv;
}

// ---------------------------------------------------------------------------
// one launch: split X, Wq, Wk, Wv, Wo
// ---------------------------------------------------------------------------
__global__ __launch_bounds__(256)
void split5(const float* __restrict__ X,  const float* __restrict__ Wq,
            const float* __restrict__ Wk, const float* __restrict__ Wv,
            const float* __restrict__ Wo, bf16* __restrict__ bf)
{
    const int b = blockIdx.x;
    const float* src;
    bf16 *h, *l;
    int base;
    if (b < 16384)      { src = X;  h = bf + OFF_XH;  l = bf + OFF_XL;  base = b; }
    else if (b < 32768) { src = Wq; h = bf + OFF_WQH; l = bf + OFF_WQL; base = b - 16384; }
    else if (b < 40960) { src = Wk; h = bf + OFF_WKH; l = bf + OFF_WKL; base = b - 32768; }
    else if (b < 49152) { src = Wv; h = bf + OFF_WVH; l = bf + OFF_WVL; base = b - 40960; }
    else                { src = Wo; h = bf + OFF_WOH; l = bf + OFF_WOL; base = b - 49152; }
    const int i = base * 256 + threadIdx.x;
    float v = src[i];
    bf16 hh = __float2bfloat16(v);
    h[i] = hh;
    l[i] = __float2bfloat16(v - __bfloat162float(hh));
}

// ---------------------------------------------------------------------------
// V transpose + split: g_v [s][kh][128] fp32 -> vt [kh][128][2048] bf16 hi/lo
// ---------------------------------------------------------------------------
__global__ __launch_bounds__(256)
void vtrans_split(const float* __restrict__ v, bf16* __restrict__ vh,
                  bf16* __restrict__ vl)
{
    __shared__ float t[32][33];
    const int s0 = blockIdx.x * 32, d0 = blockIdx.y * 32, kh = blockIdx.z;
#pragma unroll
    for (int i = 0; i < 4; i++) {
        const int row = s0 + threadIdx.y + i * 8;
        t[threadIdx.y + i * 8][threadIdx.x] =
            v[((size_t)row * NKH + kh) * HD + d0 + threadIdx.x];
    }
    __syncthreads();
#pragma unroll
    for (int i = 0; i < 4; i++) {
        const int d = d0 + threadIdx.y + i * 8;
        const int s = s0 + threadIdx.x;
        float val = t[threadIdx.x][threadIdx.y + i * 8];
        bf16 h = __float2bfloat16(val);
        const size_t o = ((size_t)kh * HD + d) * S_LEN + s;
        vh[o] = h;
        vl[o] = __float2bfloat16(val - __bfloat162float(h));
    }
}

// ---------------------------------------------------------------------------
// cp.async double-buffered HMMA GEMM mainloop
// ---------------------------------------------------------------------------
#define GST2 40
#define G2_ARR   (128 * GST2 * 2)
#define G2_STAGE (4 * G2_ARR)
#define MG2_SMEM (2 * G2_STAGE)

__device__ __forceinline__ void g2_load(uint32_t st, const bf16* gAh,
                                        const bf16* gAl, const bf16* gBh,
                                        const bf16* gBl, int K, int k0, int tid)
{
#pragma unroll
    for (int t = 0; t < 2; t++) {
        const int u = tid + (t << 8);
        const int row = u >> 2, grp = (u & 3) << 3;
        const uint32_t so = st + row * (GST2 * 2) + grp * 2;
        const size_t go = (size_t)row * K + k0 + grp;
        cpa16(so,              gAh + go);
        cpa16(so + G2_ARR,     gAl + go);
        cpa16(so + 2 * G2_ARR, gBh + go);
        cpa16(so + 3 * G2_ARR, gBl + go);
    }
    asm volatile("cp.async.commit_group;" ::: "memory");
}

__device__ __forceinline__ void g2_mainloop(
    const bf16* gAh, const bf16* gAl, const bf16* gBh, const bf16* gBl,
    int K, uint32_t sb, int tid, int warp_m, int warp_n, int lane,
    float acc[4][4][4])
{
    const int a_row = lane & 15, a_kh = (lane >> 4) << 3;
    const int b_row = (lane & 7) + ((lane >> 4) << 3), b_kh = ((lane >> 3) & 1) << 3;
    const int NC = K >> 5;

    g2_load(sb, gAh, gAl, gBh, gBl, K, 0, tid);

    for (int c = 0; c < NC; c++) {
        if (c + 1 < NC) {
            g2_load(sb + ((c + 1) & 1) * G2_STAGE, gAh, gAl, gBh, gBl, K,
                    (c + 1) << 5, tid);
            asm volatile("cp.async.wait_group 1;" ::: "memory");
        } else {
            asm volatile("cp.async.wait_group 0;" ::: "memory");
        }
        __syncthreads();
        const uint32_t st = sb + (c & 1) * G2_STAGE;
#pragma unroll
        for (int ks = 0; ks < 2; ks++) {
            const int kk = ks << 4;
            uint32_t ah[4][4], al[4][4], bh[4][2], bl[4][2];
#pragma unroll
            for (int fm = 0; fm < 4; fm++) {
                const uint32_t off =
                    st + ((warp_m * 64 + fm * 16 + a_row) * GST2 + kk + a_kh) * 2;
                ldsm4(ah[fm], off);
                ldsm4(al[fm], off + G2_ARR);
            }
#pragma unroll
            for (int fp = 0; fp < 2; fp++) {
                const uint32_t off =
                    st + ((warp_n * 32 + fp * 16 + b_row) * GST2 + kk + b_kh) * 2;
                uint32_t t[4];
                ldsm4(t, off + 2 * G2_ARR);
                bh[2*fp][0] = t[0]; bh[2*fp][1] = t[1];
                bh[2*fp+1][0] = t[2]; bh[2*fp+1][1] = t[3];
                ldsm4(t, off + 3 * G2_ARR);
                bl[2*fp][0] = t[0]; bl[2*fp][1] = t[1];
                bl[2*fp+1][0] = t[2]; bl[2*fp+1][1] = t[3];
            }
#pragma unroll
            for (int fm = 0; fm < 4; fm++)
#pragma unroll
                for (int fn = 0; fn < 4; fn++) {
                    mma16816(acc[fm][fn], ah[fm], bh[fn]);
                    mma16816(acc[fm][fn], ah[fm], bl[fn]);
                    mma16816(acc[fm][fn], al[fm], bh[fn]);
                }
        }
        __syncthreads();
    }
}

__device__ __forceinline__ void g2_epilogue(float* C, int Nout, int rbase0,
                                            int cbase0, int warp_m, int warp_n,
                                            int lane, float acc[4][4][4])
{
    const int rbase = rbase0 + warp_m * 64 + (lane >> 2);
    const int cbase = cbase0 + warp_n * 32 + ((lane & 3) << 1);
#pragma unroll
    for (int fm = 0; fm < 4; fm++) {
        const int row = rbase + fm * 16;
#pragma unroll
        for (int fn = 0; fn < 4; fn++) {
            const int col = cbase + fn * 8;
            *(float2*)(C + (size_t)row * Nout + col) =
                make_float2(acc[fm][fn][0], acc[fm][fn][1]);
            *(float2*)(C + (size_t)(row + 8) * Nout + col) =
                make_float2(acc[fm][fn][2], acc[fm][fn][3]);
        }
    }
}

// fused QKV projection: grid (32, 16)
__global__ __launch_bounds__(256)
void qkv_gemm(const bf16* __restrict__ bfarena, float* __restrict__ q,
              float* __restrict__ k, float* __restrict__ v)
{
    extern __shared__ char smc[];
    const uint32_t sb = smem_u32(smc);
    const int tid = threadIdx.x, wid = tid >> 5, lane = tid & 31;
    const int warp_m = wid >> 2, warp_n = wid & 3;
    const int bm = blockIdx.y, bn = blockIdx.x;

    const bf16* Xh = bfarena + OFF_XH;
    const bf16* Xl = bfarena + OFF_XL;
    const bf16 *Bh, *Bl;
    float* C;
    int Nout, cb;
    if (bn < 16)      { Bh = bfarena + OFF_WQH; Bl = bfarena + OFF_WQL;
                        C = q; Nout = 2048; cb = bn * 128; }
    else if (bn < 24) { Bh = bfarena + OFF_WKH; Bl = bfarena + OFF_WKL;
                        C = k; Nout = 1024; cb = (bn - 16) * 128; }
    else              { Bh = bfarena + OFF_WVH; Bl = bfarena + OFF_WVL;
                        C = v; Nout = 1024; cb = (bn - 24) * 128; }

    float acc[4][4][4];
#pragma unroll
    for (int i = 0; i < 4; i++)
#pragma unroll
        for (int j = 0; j < 4; j++)
#pragma unroll
            for (int r = 0; r < 4; r++) acc[i][j][r] = 0.f;

    g2_mainloop(Xh + (size_t)bm * 128 * HID, Xl + (size_t)bm * 128 * HID,
                Bh + (size_t)cb * HID, Bl + (size_t)cb * HID,
                HID, sb, tid, warp_m, warp_n, lane, acc);
    g2_epilogue(C, Nout, bm * 128, cb, warp_m, warp_n, lane, acc);
}

// generic NT gemm (used for Wo)
__global__ __launch_bounds__(256)
void mma_gemm2(const bf16* __restrict__ Ahi, const bf16* __restrict__ Alo,
               const bf16* __restrict__ Bhi, const bf16* __restrict__ Blo,
               float* __restrict__ C, int N, int K)
{
    extern __shared__ char smc[];
    const uint32_t sb = smem_u32(smc);
    const int tid = threadIdx.x, wid = tid >> 5, lane = tid & 31;
    const int warp_m = wid >> 2, warp_n = wid & 3;
    const int bm = blockIdx.y, bn = blockIdx.x;

    float acc[4][4][4];
#pragma unroll
    for (int i = 0; i < 4; i++)
#pragma unroll
        for (int j = 0; j < 4; j++)
#pragma unroll
            for (int r = 0; r < 4; r++) acc[i][j][r] = 0.f;

    g2_mainloop(Ahi + (size_t)bm * 128 * K, Alo + (size_t)bm * 128 * K,
                Bhi + (size_t)bn * 128 * K, Blo + (size_t)bn * 128 * K,
                K, sb, tid, warp_m, warp_n, lane, acc);
    g2_epilogue(C, N, bm * 128, bn * 128, warp_m, warp_n, lane, acc);
}

// ---------------------------------------------------------------------------
// Fused per-head RMSNorm + RoPE -> bf16 hi/lo. One launch for q AND k.
// grid (S_LEN, NH + NKH)
// ---------------------------------------------------------------------------
__global__ __launch_bounds__(128)
void norm_rope_all(const float* __restrict__ q, const float* __restrict__ k,
                   const float* __restrict__ qw, const float* __restrict__ kw,
                   const float* __restrict__ fc, const float* __restrict__ fs,
                   bf16* __restrict__ bf2a)
{
    const int s = blockIdx.x, y = blockIdx.y, d = threadIdx.x;
    const float* x;
    const float* w;
    bf16 *oh, *ol;
    int nheads, hh;
    if (y < NH) { x = q; w = qw; oh = bf2a + OFF_QH; ol = bf2a + OFF_QL;
                  nheads = NH; hh = y; }
    else        { x = k; w = kw; oh = bf2a + OFF_KH; ol = bf2a + OFF_KL;
                  nheads = NKH; hh = y - NH; }
    const float* row = x + ((size_t)s * nheads + hh) * HD;
    float v = row[d];
    float p = v * v;
#pragma unroll
    for (int o = 16; o > 0; o >>= 1) p += __shfl_xor_sync(0xffffffffu, p, o);
    __shared__ float ws[4];
    __shared__ float sx[128];
    const int lane = d & 31, wid = d >> 5;
    if (lane == 0) ws[wid] = p;
    __syncthreads();
    const float tot = ws[0] + ws[1] + ws[2] + ws[3];
    const float r = rsqrtf(tot * (1.0f / 128.0f) + 1e-6f);
    sx[d] = v * r * w[d];
    __syncthreads();
    const float c  = fc[s * 64 + (d & 63)];
    const float sn = fs[s * 64 + (d & 63)];
    float out;
    if (d < 64) out = sx[d] * c - sx[d + 64] * sn;
    else        out = sx[d - 64] * sn + sx[d] * c;
    const size_t o = ((size_t)s * nheads + hh) * HD + d;
    bf16 h = __float2bfloat16(out);
    oh[o] = h;
    ol[o] = __float2bfloat16(out - __bfloat162float(h));
}

__global__ void kvnew_kernel(const bf16* __restrict__ kh, const bf16* __restrict__ kl,
                             const float* __restrict__ v, float* __restrict__ out)
{
    const int i = blockIdx.x * 256 + threadIdx.x;
    if (i < NKH * HD) {
        const size_t o = (size_t)(S_LEN - 1) * NKH * HD + i;
        out[Y_SIZE + i] = __bfloat162float(kh[o]) + __bfloat162float(kl[o]);
        out[Y_SIZE + NKH * HD + i] = v[o];
    }
}

// ---------------------------------------------------------------------------
// GQA-paired, cp.async double-buffered HMMA flash attention.
// 256 threads: warps 0-3 -> head 2*kh (rows m0=wid*16), warps 4-7 -> head 2*kh+1.
// K/V tiles shared by both head groups, 2-stage pipeline. grid (32, 8).
// ---------------------------------------------------------------------------
#define FQSTR 136
#define FVSTR 72
#define F_KARR (64 * FQSTR)                 // 8704 bf16
#define F_VARR (128 * FVSTR)                // 9216 bf16
#define F_VOFF (2 * F_KARR)                 // 17408
#define F_ST0  (2 * 128 * FQSTR)            // 34816 (after Qh+Ql)
#define F_SS   (2 * F_KARR + 2 * F_VARR)    // 35840 per stage
#define FH2_SMEM ((F_ST0 + 2 * F_SS) * 2)   // 212992 bytes

__device__ __forceinline__ void fh_load_stage(
    uint32_t st, const bf16* __restrict__ Kh, const bf16* __restrict__ Kl,
    const bf16* __restrict__ Vth, const bf16* __restrict__ Vtl,
    int khead, int kbase, int tid)
{
#pragma unroll
    for (int t = 0; t < 4; t++) {
        const int u = tid + (t << 8);
        {
            const int row = u >> 4, c8 = (u & 15) << 3;
            const size_t g = ((size_t)(kbase + row) * NKH + khead) * HD + c8;
            const uint32_t so = st + (row * FQSTR + c8) * 2;
            cpa16(so,              Kh + g);
            cpa16(so + F_KARR * 2, Kl + g);
        }
        {
            const int row = u >> 3, c8 = (u & 7) << 3;
            const size_t g = ((size_t)khead * HD + row) * S_LEN + kbase + c8;
            const uint32_t so = st + F_VOFF * 2 + (row * FVSTR + c8) * 2;
            cpa16(so,              Vth + g);
            cpa16(so + F_VARR * 2, Vtl + g);
        }
    }
    asm volatile("cp.async.commit_group;" ::: "memory");
}

__global__ __launch_bounds__(256)
void flash_mma2(const bf16* __restrict__ Qh, const bf16* __restrict__ Ql,
                const bf16* __restrict__ Kh, const bf16* __restrict__ Kl,
                const bf16* __restrict__ Vth, const bf16* __restrict__ Vtl,
                bf16* __restrict__ Oh, bf16* __restrict__ Ol)
{
    extern __shared__ bf16 smx[];
    const uint32_t sbase = smem_u32(smx);

    const int qt = (gridDim.x - 1) - blockIdx.x;   // long tiles first
    const int khead = blockIdx.y;
    const int qbase = qt * 64;
    const int tid = threadIdx.x;
    const int wid = tid >> 5, lane = tid & 31;
    const int hsel = wid >> 2;                     // head within GQA pair
    const int h = khead * 2 + hsel;
    const int m0 = (wid & 3) * 16;

    const uint32_t baQh = sbase, baQl = sbase + F_ST0; // note: byte offsets below
    const int a_row = lane & 15, a_kh = (lane >> 4) << 3;
    const int b_row = (lane & 7) + ((lane >> 4) << 3), b_kh = ((lane >> 3) & 1) << 3;

    // ---- load Q for both heads: 128 virtual rows (row>>6 = head) ----
#pragma unroll
    for (int i = 0; i < 8; i++) {
        const int u = tid + (i << 8);
        const int row = u >> 4, c8 = (u & 15) << 3;
        const int head = row >> 6, hrow = row & 63;
        const size_t g = ((size_t)(qbase + hrow) * NH + khead * 2 + head) * HD + c8;
        const int so = row * FQSTR + c8;
        *(uint4*)(smx + so)                 = *(const uint4*)(Qh + g);
        *(uint4*)(smx + 128 * FQSTR + so)   = *(const uint4*)(Ql + g);
    }

    // prefetch first K/V stage
    fh_load_stage(sbase + F_ST0 * 2, Kh, Kl, Vth, Vtl, khead, 0, tid);

    float oacc[16][4];
#pragma unroll
    for (int i = 0; i < 16; i++)
#pragma unroll
        for (int r = 0; r < 4; r++) oacc[i][r] = 0.f;
    float mrow0 = -1e30f, mrow1 = -1e30f, lrow0 = 0.f, lrow1 = 0.f;

    const int r0 = lane >> 2;
    const int cq = (lane & 3) << 1;
    const int qrow_s = hsel * 64 + m0;   // Q smem row base for this warp

    for (int kt = 0; kt <= qt; kt++) {
        const int kbase = kt * 64;
        if (kt < qt) {
            fh_load_stage(sbase + (F_ST0 + ((kt + 1) & 1) * F_SS) * 2,
                          Kh, Kl, Vth, Vtl, khead, kbase + 64, tid);
            asm volatile("cp.async.wait_group 1;" ::: "memory");
        } else {
            asm volatile("cp.async.wait_group 0;" ::: "memory");
        }
        __syncthreads();

        const uint32_t stb = sbase + (F_ST0 + (kt & 1) * F_SS) * 2;
        const uint32_t bKh = stb, bKl = stb + F_KARR * 2;
        const uint32_t bVh = stb + F_VOFF * 2, bVl = bVh + F_VARR * 2;

        // ---- scores ----
        float sacc[8][4];
#pragma unroll
        for (int f = 0; f < 8; f++)
#pragma unroll
            for (int r = 0; r < 4; r++) sacc[f][r] = 0.f;

#pragma unroll
        for (int kf = 0; kf < 8; kf++) {
            const int kk = kf << 4;
            uint32_t ah[4], al[4];
            const uint32_t qoff = ((qrow_s + a_row) * FQSTR + kk + a_kh) * 2;
            ldsm4(ah, sbase + qoff);
            ldsm4(al, sbase + 128 * FQSTR * 2 + qoff);
#pragma unroll
            for (int fp = 0; fp < 4; fp++) {
                const uint32_t off = ((fp * 16 + b_row) * FQSTR + kk + b_kh) * 2;
                uint32_t th[4], tl[4];
                ldsm4(th, bKh + off);
                ldsm4(tl, bKl + off);
                uint32_t bh0[2] = {th[0], th[1]}, bh1[2] = {th[2], th[3]};
                uint32_t bl0[2] = {tl[0], tl[1]}, bl1[2] = {tl[2], tl[3]};
                mma16816(sacc[2*fp],   ah, bh0);
                mma16816(sacc[2*fp],   ah, bl0);
                mma16816(sacc[2*fp],   al, bh0);
                mma16816(sacc[2*fp+1], ah, bh1);
                mma16816(sacc[2*fp+1], ah, bl1);
                mma16816(sacc[2*fp+1], al, bh1);
            }
        }

#pragma unroll
        for (int f = 0; f < 8; f++)
#pragma unroll
            for (int r = 0; r < 4; r++) sacc[f][r] *= SCALE;

        if (kt == qt) {
#pragma unroll
            for (int f = 0; f < 8; f++) {
                const int col = (f << 3) + cq;
                const int row0g = m0 + r0, row1g = m0 + r0 + 8;
                if (col     > row0g) sacc[f][0] = -1e9f;
                if (col + 1 > row0g) sacc[f][1] = -1e9f;
                if (col     > row1g) sacc[f][2] = -1e9f;
                if (col + 1 > row1g) sacc[f][3] = -1e9f;
            }
        }

        float tm0 = -1e30f, tm1 = -1e30f;
#pragma unroll
        for (int f = 0; f < 8; f++) {
            tm0 = fmaxf(tm0, fmaxf(sacc[f][0], sacc[f][1]));
            tm1 = fmaxf(tm1, fmaxf(sacc[f][2], sacc[f][3]));
        }
        tm0 = fmaxf(tm0, __shfl_xor_sync(0xffffffffu, tm0, 1));
        tm0 = fmaxf(tm0, __shfl_xor_sync(0xffffffffu, tm0, 2));
        tm1 = fmaxf(tm1, __shfl_xor_sync(0xffffffffu, tm1, 1));
        tm1 = fmaxf(tm1, __shfl_xor_sync(0xffffffffu, tm1, 2));

        const float mn0 = fmaxf(mrow0, tm0), mn1 = fmaxf(mrow1, tm1);
        const float cr0 = __expf(mrow0 - mn0), cr1 = __expf(mrow1 - mn1);
        float rs0 = 0.f, rs1 = 0.f;
#pragma unroll
        for (int f = 0; f < 8; f++) {
            sacc[f][0] = __expf(sacc[f][0] - mn0);
            sacc[f][1] = __expf(sacc[f][1] - mn0);
            sacc[f][2] = __expf(sacc[f][2] - mn1);
            sacc[f][3] = __expf(sacc[f][3] - mn1);
            rs0 += sacc[f][0] + sacc[f][1];
            rs1 += sacc[f][2] + sacc[f][3];
        }
        rs0 += __shfl_xor_sync(0xffffffffu, rs0, 1);
        rs0 += __shfl_xor_sync(0xffffffffu, rs0, 2);
        rs1 += __shfl_xor_sync(0xffffffffu, rs1, 1);
        rs1 += __shfl_xor_sync(0xffffffffu, rs1, 2);
        lrow0 = lrow0 * cr0 + rs0;
        lrow1 = lrow1 * cr1 + rs1;
        mrow0 = mn0; mrow1 = mn1;
#pragma unroll
        for (int i = 0; i < 16; i++) {
            oacc[i][0] *= cr0; oacc[i][1] *= cr0;
            oacc[i][2] *= cr1; oacc[i][3] *= cr1;
        }

        // ---- repack P ----
        uint32_t ph[4][4], pl[4][4];
#pragma unroll
        for (int t = 0; t < 4; t++) {
            split2(sacc[2*t][0],   sacc[2*t][1],   ph[t][0], pl[t][0]);
            split2(sacc[2*t][2],   sacc[2*t][3],   ph[t][1], pl[t][1]);
            split2(sacc[2*t+1][0], sacc[2*t+1][1], ph[t][2], pl[t][2]);
            split2(sacc[2*t+1][2], sacc[2*t+1][3], ph[t][3], pl[t][3]);
        }

        // ---- O += P @ V ----
#pragma unroll
        for (int dp = 0; dp < 8; dp++) {
#pragma unroll
            for (int t = 0; t < 4; t++) {
                const uint32_t off = ((dp * 16 + b_row) * FVSTR + t * 16 + b_kh) * 2;
                uint32_t th[4], tl[4];
                ldsm4(th, bVh + off);
                ldsm4(tl, bVl + off);
                uint32_t bh0[2] = {th[0], th[1]}, bh1[2] = {th[2], th[3]};
                uint32_t bl0[2] = {tl[0], tl[1]}, bl1[2] = {tl[2], tl[3]};
                mma16816(oacc[2*dp],   ph[t], bh0);
                mma16816(oacc[2*dp],   ph[t], bl0);
                mma16816(oacc[2*dp],   pl[t], bh0);
                mma16816(oacc[2*dp+1], ph[t], bh1);
                mma16816(oacc[2*dp+1], ph[t], bl1);
                mma16816(oacc[2*dp+1], pl[t], bh1);
            }
        }
        __syncthreads();   // stage (kt&1) free for prefetch of kt+2
    }

    // epilogue: normalize + bf16 hi/lo split into attn arena
    const float inv0 = 1.0f / lrow0, inv1 = 1.0f / lrow1;
    const int gr0 = qbase + m0 + r0, gr1 = gr0 + 8;
#pragma unroll
    for (int nf = 0; nf < 16; nf++) {
        const int col = (nf << 3) + cq;
        const size_t o0 = ((size_t)gr0 * NH + h) * HD + col;
        const size_t o1 = ((size_t)gr1 * NH + h) * HD + col;
        uint32_t hh, ll;
        split2(oacc[nf][0] * inv0, oacc[nf][1] * inv0, hh, ll);
        *(uint32_t*)(Oh + o0) = hh;
        *(uint32_t*)(Ol + o0) = ll;
        split2(oacc[nf][2] * inv1, oacc[nf][3] * inv1, hh, ll);
        *(uint32_t*)(Oh + o1) = hh;
        *(uint32_t*)(Ol + o1) = ll;
    }
}

// ---------------------------------------------------------------------------
extern "C" void kernel_launch(void* const* d_in, const int* in_sizes, int n_in,
                              void* d_out, int out_size)
{
    const float* X  = (const float*)d_in[0];
    const float* fc = (const float*)d_in[1];
    const float* fs = (const float*)d_in[2];
    // d_in[3] atten_mask unused: exactly causal, applied analytically
    const float* Wq = (const float*)d_in[4];
    const float* Wk = (const float*)d_in[5];
    const float* Wv = (const float*)d_in[6];
    const float* Wo = (const float*)d_in[7];
    const float* qw = (const float*)d_in[8];
    const float* kw = (const float*)d_in[9];
    float* out = (float*)d_out;

    float *q, *k, *v;
    bf16 *bf, *bf2;
    cudaGetSymbolAddress((void**)&q, g_q);
    cudaGetSymbolAddress((void**)&k, g_k);
    cudaGetSymbolAddress((void**)&v, g_v);
    cudaGetSymbolAddress((void**)&bf, g_bf);
    cudaGetSymbolAddress((void**)&bf2, g_bf2);

    cudaFuncSetAttribute(qkv_gemm, cudaFuncAttributeMaxDynamicSharedMemorySize,
                         MG2_SMEM);
    cudaFuncSetAttribute(mma_gemm2, cudaFuncAttributeMaxDynamicSharedMemorySize,
                         MG2_SMEM);
    cudaFuncSetAttribute(flash_mma2, cudaFuncAttributeMaxDynamicSharedMemorySize,
                         FH2_SMEM);

    // split X + all weights to bf16 hi/lo (one launch)
    split5<<<65536, 256>>>(X, Wq, Wk, Wv, Wo, bf);

    // fused QKV projection (cp.async double-buffered HMMA)
    qkv_gemm<<<dim3(32, 16), 256, MG2_SMEM>>>(bf, q, k, v);

    // RMSNorm + RoPE for q AND k, fused with bf16 hi/lo split (one launch)
    norm_rope_all<<<dim3(S_LEN, NH + NKH), 128>>>(q, k, qw, kw, fc, fs, bf2);

    // k_new / v_new tail outputs
    kvnew_kernel<<<4, 256>>>(bf2 + OFF_KH, bf2 + OFF_KL, v, out);

    // V transpose + split
    vtrans_split<<<dim3(64, 4, 8), dim3(32, 8)>>>(v, bf2 + OFF_VTH, bf2 + OFF_VTL);

    // GQA-paired double-buffered HMMA flash attention
    flash_mma2<<<dim3(32, 8), 256, FH2_SMEM>>>(
        bf2 + OFF_QH, bf2 + OFF_QL, bf2 + OFF_KH, bf2 + OFF_KL,
        bf2 + OFF_VTH, bf2 + OFF_VTL, bf + OFF_ATH, bf + OFF_ATL);

    // output projection directly into d_out
    mma_gemm2<<<dim3(16, 16), 256, MG2_SMEM>>>(bf + OFF_ATH, bf + OFF_ATL,
                                               bf + OFF_WOH, bf + OFF_WOL,
                                               out, HID, NH * HD);
}

// round 17
// speedup vs baseline: 3.3971x; 1.0788x over previous
#include <cuda_runtime.h>
#include <cuda_fp16.h>
#include <cstdint>

typedef __half f16;

#define S_LEN 2048
#define HID   2048
#define NH    16
#define NKH   8
#define HD    128
#define SCALE 0.08838834764831845f
#define Y_SIZE (S_LEN * NH * HD)

// ---------------- fp32 scratch ----------------
__device__ float g_q[S_LEN * NH * HD];
__device__ float g_k[S_LEN * NKH * HD];
__device__ float g_v[S_LEN * NKH * HD];

// ---------------- f16 split arena #1 (gemm operands) ----------------
#define OFF_XH   0u
#define OFF_XL   4194304u
#define OFF_WQH  8388608u
#define OFF_WQL  12582912u
#define OFF_WKH  16777216u
#define OFF_WKL  18874368u
#define OFF_WVH  20971520u
#define OFF_WVL  23068672u
#define OFF_WOH  25165824u
#define OFF_WOL  29360128u
#define OFF_ATH  33554432u
#define OFF_ATL  37748736u
__device__ __align__(1024) f16 g_bf[41943040];

// ---------------- f16 split arena #2 (flash operands) ----------------
#define OFF_QH   0u
#define OFF_QL   4194304u
#define OFF_KH   8388608u
#define OFF_KL   10485760u
#define OFF_VTH  12582912u        // [kh][d][s] transposed, hi only
__device__ __align__(1024) f16 g_bf2[16777216];

__device__ __forceinline__ uint32_t smem_u32(const void* p) {
    uint32_t a;
    asm("{ .reg .u64 t; cvta.to.shared.u64 t, %1; cvt.u32.u64 %0, t; }"
        : "=r"(a) : "l"(p));
    return a;
}
__device__ __forceinline__ void ldsm4(uint32_t* r, uint32_t addr) {
    asm volatile("ldmatrix.sync.aligned.m8n8.x4.shared.b16 {%0,%1,%2,%3}, [%4];"
                 : "=r"(r[0]), "=r"(r[1]), "=r"(r[2]), "=r"(r[3]) : "r"(addr));
}
__device__ __forceinline__ void mma16816(float* c, const uint32_t* a, const uint32_t* b) {
    asm volatile("mma.sync.aligned.m16n8k16.row.col.f32.f16.f16.f32 "
                 "{%0,%1,%2,%3}, {%4,%5,%6,%7}, {%8,%9}, {%0,%1,%2,%3};"
                 : "+f"(c[0]), "+f"(c[1]), "+f"(c[2]), "+f"(c[3])
                 : "r"(a[0]), "r"(a[1]), "r"(a[2]), "r"(a[3]), "r"(b[0]), "r"(b[1]));
}
__device__ __forceinline__ void cpa16(uint32_t s, const void* g) {
    asm volatile("cp.async.cg.shared.global [%0], [%1], 16;" :: "r"(s), "l"(g));
}
__device__ __forceinline__ void split2(float a, float b, uint32_t& h, uint32_t& l) {
    f16 ha = __float2half_rn(a), hb = __float2half_rn(b);
    float la = a - __half2float(ha), lb = b - __half2float(hb);
    __half2 hv = __halves2half2(ha, hb);
    __half2 lv = __floats2half2_rn(la, lb);
    h = *(uint32_t*)&hv;
    l = *(uint32_t*)&lv;
}

// ---------------------------------------------------------------------------
// one launch: split X, Wq, Wk, Wv, Wo to f16 hi/lo
// ---------------------------------------------------------------------------
__global__ __launch_bounds__(256)
void split5(const float* __restrict__ X,  const float* __restrict__ Wq,
            const float* __restrict__ Wk, const float* __restrict__ Wv,
            const float* __restrict__ Wo, f16* __restrict__ bf)
{
    const int b = blockIdx.x;
    const float* src;
    f16 *h, *l;
    int base;
    if (b < 16384)      { src = X;  h = bf + OFF_XH;  l = bf + OFF_XL;  base = b; }
    else if (b < 32768) { src = Wq; h = bf + OFF_WQH; l = bf + OFF_WQL; base = b - 16384; }
    else if (b < 40960) { src = Wk; h = bf + OFF_WKH; l = bf + OFF_WKL; base = b - 32768; }
    else if (b < 49152) { src = Wv; h = bf + OFF_WVH; l = bf + OFF_WVL; base = b - 40960; }
    else                { src = Wo; h = bf + OFF_WOH; l = bf + OFF_WOL; base = b - 49152; }
    const int i = base * 256 + threadIdx.x;
    float v = src[i];
    f16 hh = __float2half_rn(v);
    h[i] = hh;
    l[i] = __float2half_rn(v - __half2float(hh));
}

// ---------------------------------------------------------------------------
// V transpose + split (hi only): g_v [s][kh][128] fp32 -> vt [kh][128][2048]
// ---------------------------------------------------------------------------
__global__ __launch_bounds__(256)
void vtrans_split(const float* __restrict__ v, f16* __restrict__ vh)
{
    __shared__ float t[32][33];
    const int s0 = blockIdx.x * 32, d0 = blockIdx.y * 32, kh = blockIdx.z;
#pragma unroll
    for (int i = 0; i < 4; i++) {
        const int row = s0 + threadIdx.y + i * 8;
        t[threadIdx.y + i * 8][threadIdx.x] =
            v[((size_t)row * NKH + kh) * HD + d0 + threadIdx.x];
    }
    __syncthreads();
#pragma unroll
    for (int i = 0; i < 4; i++) {
        const int d = d0 + threadIdx.y + i * 8;
        const int s = s0 + threadIdx.x;
        float val = t[threadIdx.x][threadIdx.y + i * 8];
        vh[((size_t)kh * HD + d) * S_LEN + s] = __float2half_rn(val);
    }
}

// ---------------------------------------------------------------------------
// cp.async double-buffered HMMA GEMM mainloop, templated on product count.
// NPROD=3: AhBh + AhBl + AlBh.  NPROD=2: AhBh + AlBh  (= A*Bh).
// ---------------------------------------------------------------------------
#define GST2 40
#define G2_ARR   (128 * GST2 * 2)
#define G2_STAGE (4 * G2_ARR)
#define MG2_SMEM (2 * G2_STAGE)

__device__ __forceinline__ void g2_load(uint32_t st, const f16* gAh,
                                        const f16* gAl, const f16* gBh,
                                        const f16* gBl, int K, int k0, int tid)
{
#pragma unroll
    for (int t = 0; t < 2; t++) {
        const int u = tid + (t << 8);
        const int row = u >> 2, grp = (u & 3) << 3;
        const uint32_t so = st + row * (GST2 * 2) + grp * 2;
        const size_t go = (size_t)row * K + k0 + grp;
        cpa16(so,              gAh + go);
        cpa16(so + G2_ARR,     gAl + go);
        cpa16(so + 2 * G2_ARR, gBh + go);
        cpa16(so + 3 * G2_ARR, gBl + go);
    }
    asm volatile("cp.async.commit_group;" ::: "memory");
}

template <int NPROD>
__device__ __forceinline__ void g2_mainloop(
    const f16* gAh, const f16* gAl, const f16* gBh, const f16* gBl,
    int K, uint32_t sb, int tid, int warp_m, int warp_n, int lane,
    float acc[4][4][4])
{
    const int a_row = lane & 15, a_kh = (lane >> 4) << 3;
    const int b_row = (lane & 7) + ((lane >> 4) << 3), b_kh = ((lane >> 3) & 1) << 3;
    const int NC = K >> 5;

    g2_load(sb, gAh, gAl, gBh, gBl, K, 0, tid);

    for (int c = 0; c < NC; c++) {
        if (c + 1 < NC) {
            g2_load(sb + ((c + 1) & 1) * G2_STAGE, gAh, gAl, gBh, gBl, K,
                    (c + 1) << 5, tid);
            asm volatile("cp.async.wait_group 1;" ::: "memory");
        } else {
            asm volatile("cp.async.wait_group 0;" ::: "memory");
        }
        __syncthreads();
        const uint32_t st = sb + (c & 1) * G2_STAGE;
#pragma unroll
        for (int ks = 0; ks < 2; ks++) {
            const int kk = ks << 4;
            uint32_t ah[4][4], al[4][4], bh[4][2], bl[4][2];
#pragma unroll
            for (int fm = 0; fm < 4; fm++) {
                const uint32_t off =
                    st + ((warp_m * 64 + fm * 16 + a_row) * GST2 + kk + a_kh) * 2;
                ldsm4(ah[fm], off);
                ldsm4(al[fm], off + G2_ARR);
            }
#pragma unroll
            for (int fp = 0; fp < 2; fp++) {
                const uint32_t off =
                    st + ((warp_n * 32 + fp * 16 + b_row) * GST2 + kk + b_kh) * 2;
                uint32_t t[4];
                ldsm4(t, off + 2 * G2_ARR);
                bh[2*fp][0] = t[0]; bh[2*fp][1] = t[1];
                bh[2*fp+1][0] = t[2]; bh[2*fp+1][1] = t[3];
                if (NPROD == 3) {
                    ldsm4(t, off + 3 * G2_ARR);
                    bl[2*fp][0] = t[0]; bl[2*fp][1] = t[1];
                    bl[2*fp+1][0] = t[2]; bl[2*fp+1][1] = t[3];
                }
            }
#pragma unroll
            for (int fm = 0; fm < 4; fm++)
#pragma unroll
                for (int fn = 0; fn < 4; fn++) {
                    mma16816(acc[fm][fn], ah[fm], bh[fn]);
                    if (NPROD == 3) mma16816(acc[fm][fn], ah[fm], bl[fn]);
                    mma16816(acc[fm][fn], al[fm], bh[fn]);
                }
        }
        __syncthreads();
    }
}

__device__ __forceinline__ void g2_epilogue(float* C, int Nout, int rbase0,
                                            int cbase0, int warp_m, int warp_n,
                                            int lane, float acc[4][4][4])
{
    const int rbase = rbase0 + warp_m * 64 + (lane >> 2);
    const int cbase = cbase0 + warp_n * 32 + ((lane & 3) << 1);
#pragma unroll
    for (int fm = 0; fm < 4; fm++) {
        const int row = rbase + fm * 16;
#pragma unroll
        for (int fn = 0; fn < 4; fn++) {
            const int col = cbase + fn * 8;
            *(float2*)(C + (size_t)row * Nout + col) =
                make_float2(acc[fm][fn][0], acc[fm][fn][1]);
            *(float2*)(C + (size_t)(row + 8) * Nout + col) =
                make_float2(acc[fm][fn][2], acc[fm][fn][3]);
        }
    }
}

// fused QKV projection: grid (32, 16). q,k: 3-prod (feeds softmax); v: 2-prod.
__global__ __launch_bounds__(256)
void qkv_gemm(const f16* __restrict__ bfarena, float* __restrict__ q,
              float* __restrict__ k, float* __restrict__ v)
{
    extern __shared__ char smc[];
    const uint32_t sb = smem_u32(smc);
    const int tid = threadIdx.x, wid = tid >> 5, lane = tid & 31;
    const int warp_m = wid >> 2, warp_n = wid & 3;
    const int bm = blockIdx.y, bn = blockIdx.x;

    const f16* Xh = bfarena + OFF_XH;
    const f16* Xl = bfarena + OFF_XL;
    const f16 *Bh, *Bl;
    float* C;
    int Nout, cb;
    if (bn < 16)      { Bh = bfarena + OFF_WQH; Bl = bfarena + OFF_WQL;
                        C = q; Nout = 2048; cb = bn * 128; }
    else if (bn < 24) { Bh = bfarena + OFF_WKH; Bl = bfarena + OFF_WKL;
                        C = k; Nout = 1024; cb = (bn - 16) * 128; }
    else              { Bh = bfarena + OFF_WVH; Bl = bfarena + OFF_WVL;
                        C = v; Nout = 1024; cb = (bn - 24) * 128; }

    float acc[4][4][4];
#pragma unroll
    for (int i = 0; i < 4; i++)
#pragma unroll
        for (int j = 0; j < 4; j++)
#pragma unroll
            for (int r = 0; r < 4; r++) acc[i][j][r] = 0.f;

    if (bn < 24)
        g2_mainloop<3>(Xh + (size_t)bm * 128 * HID, Xl + (size_t)bm * 128 * HID,
                       Bh + (size_t)cb * HID, Bl + (size_t)cb * HID,
                       HID, sb, tid, warp_m, warp_n, lane, acc);
    else
        g2_mainloop<2>(Xh + (size_t)bm * 128 * HID, Xl + (size_t)bm * 128 * HID,
                       Bh + (size_t)cb * HID, Bl + (size_t)cb * HID,
                       HID, sb, tid, warp_m, warp_n, lane, acc);
    g2_epilogue(C, Nout, bm * 128, cb, warp_m, warp_n, lane, acc);
}

// Wo gemm: 2-prod
__global__ __launch_bounds__(256)
void mma_gemm2(const f16* __restrict__ Ahi, const f16* __restrict__ Alo,
               const f16* __restrict__ Bhi, const f16* __restrict__ Blo,
               float* __restrict__ C, int N, int K)
{
    extern __shared__ char smc[];
    const uint32_t sb = smem_u32(smc);
    const int tid = threadIdx.x, wid = tid >> 5, lane = tid & 31;
    const int warp_m = wid >> 2, warp_n = wid & 3;
    const int bm = blockIdx.y, bn = blockIdx.x;

    float acc[4][4][4];
#pragma unroll
    for (int i = 0; i < 4; i++)
#pragma unroll
        for (int j = 0; j < 4; j++)
#pragma unroll
            for (int r = 0; r < 4; r++) acc[i][j][r] = 0.f;

    g2_mainloop<2>(Ahi + (size_t)bm * 128 * K, Alo + (size_t)bm * 128 * K,
                   Bhi + (size_t)bn * 128 * K, Blo + (size_t)bn * 128 * K,
                   K, sb, tid, warp_m, warp_n, lane, acc);
    g2_epilogue(C, N, bm * 128, bn * 128, warp_m, warp_n, lane, acc);
}

// ---------------------------------------------------------------------------
// Fused per-head RMSNorm + RoPE -> f16 hi/lo. One launch for q AND k.
// ---------------------------------------------------------------------------
__global__ __launch_bounds__(128)
void norm_rope_all(const float* __restrict__ q, const float* __restrict__ k,
                   const float* __restrict__ qw, const float* __restrict__ kw,
                   const float* __restrict__ fc, const float* __restrict__ fs,
                   f16* __restrict__ bf2a)
{
    const int s = blockIdx.x, y = blockIdx.y, d = threadIdx.x;
    const float* x;
    const float* w;
    f16 *oh, *ol;
    int nheads, hh;
    if (y < NH) { x = q; w = qw; oh = bf2a + OFF_QH; ol = bf2a + OFF_QL;
                  nheads = NH; hh = y; }
    else        { x = k; w = kw; oh = bf2a + OFF_KH; ol = bf2a + OFF_KL;
                  nheads = NKH; hh = y - NH; }
    const float* row = x + ((size_t)s * nheads + hh) * HD;
    float v = row[d];
    float p = v * v;
#pragma unroll
    for (int o = 16; o > 0; o >>= 1) p += __shfl_xor_sync(0xffffffffu, p, o);
    __shared__ float ws[4];
    __shared__ float sx[128];
    const int lane = d & 31, wid = d >> 5;
    if (lane == 0) ws[wid] = p;
    __syncthreads();
    const float tot = ws[0] + ws[1] + ws[2] + ws[3];
    const float r = rsqrtf(tot * (1.0f / 128.0f) + 1e-6f);
    sx[d] = v * r * w[d];
    __syncthreads();
    const float c  = fc[s * 64 + (d & 63)];
    const float sn = fs[s * 64 + (d & 63)];
    float out;
    if (d < 64) out = sx[d] * c - sx[d + 64] * sn;
    else        out = sx[d - 64] * sn + sx[d] * c;
    const size_t o = ((size_t)s * nheads + hh) * HD + d;
    f16 h = __float2half_rn(out);
    oh[o] = h;
    ol[o] = __float2half_rn(out - __half2float(h));
}

__global__ void kvnew_kernel(const f16* __restrict__ kh, const f16* __restrict__ kl,
                             const float* __restrict__ v, float* __restrict__ out)
{
    const int i = blockIdx.x * 256 + threadIdx.x;
    if (i < NKH * HD) {
        const size_t o = (size_t)(S_LEN - 1) * NKH * HD + i;
        out[Y_SIZE + i] = __half2float(kh[o]) + __half2float(kl[o]);
        out[Y_SIZE + NKH * HD + i] = v[o];
    }
}

// ---------------------------------------------------------------------------
// GQA-paired, cp.async double-buffered HMMA flash attention (fp16).
// Scores: 3-prod (Qh,Ql x Kh,Kl). PV: 2-prod (P full x Vh only).
// Stage layout: [Kh | Kl | Vh]. grid (32, 8), 256 threads.
// ---------------------------------------------------------------------------
#define FQSTR 136
#define FVSTR 72
#define F_KARR (64 * FQSTR)                 // 8704 elems
#define F_VARR (128 * FVSTR)                // 9216 elems
#define F_VOFF (2 * F_KARR)
#define F_ST0  (2 * 128 * FQSTR)            // 34816 (Qh+Ql)
#define F_SS   (2 * F_KARR + F_VARR)        // 26624 per stage
#define FH2_SMEM ((F_ST0 + 2 * F_SS) * 2)   // 176128 bytes

__device__ __forceinline__ void fh_load_stage(
    uint32_t st, const f16* __restrict__ Kh, const f16* __restrict__ Kl,
    const f16* __restrict__ Vth, int khead, int kbase, int tid)
{
#pragma unroll
    for (int t = 0; t < 4; t++) {
        const int u = tid + (t << 8);
        {
            const int row = u >> 4, c8 = (u & 15) << 3;
            const size_t g = ((size_t)(kbase + row) * NKH + khead) * HD + c8;
            const uint32_t so = st + (row * FQSTR + c8) * 2;
            cpa16(so,              Kh + g);
            cpa16(so + F_KARR * 2, Kl + g);
        }
        {
            const int row = u >> 3, c8 = (u & 7) << 3;
            const size_t g = ((size_t)khead * HD + row) * S_LEN + kbase + c8;
            cpa16(st + F_VOFF * 2 + (row * FVSTR + c8) * 2, Vth + g);
        }
    }
    asm volatile("cp.async.commit_group;" ::: "memory");
}

__global__ __launch_bounds__(256)
void flash_mma2(const f16* __restrict__ Qh, const f16* __restrict__ Ql,
                const f16* __restrict__ Kh, const f16* __restrict__ Kl,
                const f16* __restrict__ Vth,
                f16* __restrict__ Oh, f16* __restrict__ Ol)
{
    extern __shared__ f16 smx[];
    const uint32_t sbase = smem_u32(smx);

    const int qt = (gridDim.x - 1) - blockIdx.x;
    const int khead = blockIdx.y;
    const int qbase = qt * 64;
    const int tid = threadIdx.x;
    const int wid = tid >> 5, lane = tid & 31;
    const int hsel = wid >> 2;
    const int h = khead * 2 + hsel;
    const int m0 = (wid & 3) * 16;

    const int a_row = lane & 15, a_kh = (lane >> 4) << 3;
    const int b_row = (lane & 7) + ((lane >> 4) << 3), b_kh = ((lane >> 3) & 1) << 3;

    // Q for both heads: 128 virtual rows
#pragma unroll
    for (int i = 0; i < 8; i++) {
        const int u = tid + (i << 8);
        const int row = u >> 4, c8 = (u & 15) << 3;
        const int head = row >> 6, hrow = row & 63;
        const size_t g = ((size_t)(qbase + hrow) * NH + khead * 2 + head) * HD + c8;
        const int so = row * FQSTR + c8;
        *(uint4*)(smx + so)               = *(const uint4*)(Qh + g);
        *(uint4*)(smx + 128 * FQSTR + so) = *(const uint4*)(Ql + g);
    }

    fh_load_stage(sbase + F_ST0 * 2, Kh, Kl, Vth, khead, 0, tid);

    float oacc[16][4];
#pragma unroll
    for (int i = 0; i < 16; i++)
#pragma unroll
        for (int r = 0; r < 4; r++) oacc[i][r] = 0.f;
    float mrow0 = -1e30f, mrow1 = -1e30f, lrow0 = 0.f, lrow1 = 0.f;

    const int r0 = lane >> 2;
    const int cq = (lane & 3) << 1;
    const int qrow_s = hsel * 64 + m0;

    for (int kt = 0; kt <= qt; kt++) {
        if (kt < qt) {
            fh_load_stage(sbase + (F_ST0 + ((kt + 1) & 1) * F_SS) * 2,
                          Kh, Kl, Vth, khead, (kt + 1) * 64, tid);
            asm volatile("cp.async.wait_group 1;" ::: "memory");
        } else {
            asm volatile("cp.async.wait_group 0;" ::: "memory");
        }
        __syncthreads();

        const uint32_t stb = sbase + (F_ST0 + (kt & 1) * F_SS) * 2;
        const uint32_t bKh = stb, bKl = stb + F_KARR * 2;
        const uint32_t bVh = stb + F_VOFF * 2;

        // ---- scores (3-prod) ----
        float sacc[8][4];
#pragma unroll
        for (int f = 0; f < 8; f++)
#pragma unroll
            for (int r = 0; r < 4; r++) sacc[f][r] = 0.f;

#pragma unroll
        for (int kf = 0; kf < 8; kf++) {
            const int kk = kf << 4;
            uint32_t ah[4], al[4];
            const uint32_t qoff = ((qrow_s + a_row) * FQSTR + kk + a_kh) * 2;
            ldsm4(ah, sbase + qoff);
            ldsm4(al, sbase + 128 * FQSTR * 2 + qoff);
#pragma unroll
            for (int fp = 0; fp < 4; fp++) {
                const uint32_t off = ((fp * 16 + b_row) * FQSTR + kk + b_kh) * 2;
                uint32_t th[4], tl[4];
                ldsm4(th, bKh + off);
                ldsm4(tl, bKl + off);
                uint32_t bh0[2] = {th[0], th[1]}, bh1[2] = {th[2], th[3]};
                uint32_t bl0[2] = {tl[0], tl[1]}, bl1[2] = {tl[2], tl[3]};
                mma16816(sacc[2*fp],   ah, bh0);
                mma16816(sacc[2*fp],   ah, bl0);
                mma16816(sacc[2*fp],   al, bh0);
                mma16816(sacc[2*fp+1], ah, bh1);
                mma16816(sacc[2*fp+1], ah, bl1);
                mma16816(sacc[2*fp+1], al, bh1);
            }
        }

#pragma unroll
        for (int f = 0; f < 8; f++)
#pragma unroll
            for (int r = 0; r < 4; r++) sacc[f][r] *= SCALE;

        if (kt == qt) {
#pragma unroll
            for (int f = 0; f < 8; f++) {
                const int col = (f << 3) + cq;
                const int row0g = m0 + r0, row1g = m0 + r0 + 8;
                if (col     > row0g) sacc[f][0] = -1e9f;
                if (col + 1 > row0g) sacc[f][1] = -1e9f;
                if (col     > row1g) sacc[f][2] = -1e9f;
                if (col + 1 > row1g) sacc[f][3] = -1e9f;
            }
        }

        float tm0 = -1e30f, tm1 = -1e30f;
#pragma unroll
        for (int f = 0; f < 8; f++) {
            tm0 = fmaxf(tm0, fmaxf(sacc[f][0], sacc[f][1]));
            tm1 = fmaxf(tm1, fmaxf(sacc[f][2], sacc[f][3]));
        }
        tm0 = fmaxf(tm0, __shfl_xor_sync(0xffffffffu, tm0, 1));
        tm0 = fmaxf(tm0, __shfl_xor_sync(0xffffffffu, tm0, 2));
        tm1 = fmaxf(tm1, __shfl_xor_sync(0xffffffffu, tm1, 1));
        tm1 = fmaxf(tm1, __shfl_xor_sync(0xffffffffu, tm1, 2));

        const float mn0 = fmaxf(mrow0, tm0), mn1 = fmaxf(mrow1, tm1);
        const float cr0 = __expf(mrow0 - mn0), cr1 = __expf(mrow1 - mn1);
        float rs0 = 0.f, rs1 = 0.f;
#pragma unroll
        for (int f = 0; f < 8; f++) {
            sacc[f][0] = __expf(sacc[f][0] - mn0);
            sacc[f][1] = __expf(sacc[f][1] - mn0);
            sacc[f][2] = __expf(sacc[f][2] - mn1);
            sacc[f][3] = __expf(sacc[f][3] - mn1);
            rs0 += sacc[f][0] + sacc[f][1];
            rs1 += sacc[f][2] + sacc[f][3];
        }
        rs0 += __shfl_xor_sync(0xffffffffu, rs0, 1);
        rs0 += __shfl_xor_sync(0xffffffffu, rs0, 2);
        rs1 += __shfl_xor_sync(0xffffffffu, rs1, 1);
        rs1 += __shfl_xor_sync(0xffffffffu, rs1, 2);
        lrow0 = lrow0 * cr0 + rs0;
        lrow1 = lrow1 * cr1 + rs1;
        mrow0 = mn0; mrow1 = mn1;
#pragma unroll
        for (int i = 0; i < 16; i++) {
            oacc[i][0] *= cr0; oacc[i][1] *= cr0;
            oacc[i][2] *= cr1; oacc[i][3] *= cr1;
        }

        // ---- repack P (f16 hi/lo) ----
        uint32_t ph[4][4], pl[4][4];
#pragma unroll
        for (int t = 0; t < 4; t++) {
            split2(sacc[2*t][0],   sacc[2*t][1],   ph[t][0], pl[t][0]);
            split2(sacc[2*t][2],   sacc[2*t][3],   ph[t][1], pl[t][1]);
            split2(sacc[2*t+1][0], sacc[2*t+1][1], ph[t][2], pl[t][2]);
            split2(sacc[2*t+1][2], sacc[2*t+1][3], ph[t][3], pl[t][3]);
        }

        // ---- O += P @ Vh (2-prod) ----
#pragma unroll
        for (int dp = 0; dp < 8; dp++) {
#pragma unroll
            for (int t = 0; t < 4; t++) {
                const uint32_t off = ((dp * 16 + b_row) * FVSTR + t * 16 + b_kh) * 2;
                uint32_t th[4];
                ldsm4(th, bVh + off);
                uint32_t bh0[2] = {th[0], th[1]}, bh1[2] = {th[2], th[3]};
                mma16816(oacc[2*dp],   ph[t], bh0);
                mma16816(oacc[2*dp],   pl[t], bh0);
                mma16816(oacc[2*dp+1], ph[t], bh1);
                mma16816(oacc[2*dp+1], pl[t], bh1);
            }
        }
        __syncthreads();
    }

    // epilogue: normalize + f16 hi/lo split into attn arena
    const float inv0 = 1.0f / lrow0, inv1 = 1.0f / lrow1;
    const int gr0 = qbase + m0 + r0, gr1 = gr0 + 8;
#pragma unroll
    for (int nf = 0; nf < 16; nf++) {
        const int col = (nf << 3) + cq;
        const size_t o0 = ((size_t)gr0 * NH + h) * HD + col;
        const size_t o1 = ((size_t)gr1 * NH + h) * HD + col;
        uint32_t hh, ll;
        split2(oacc[nf][0] * inv0, oacc[nf][1] * inv0, hh, ll);
        *(uint32_t*)(Oh + o0) = hh;
        *(uint32_t*)(Ol + o0) = ll;
        split2(oacc[nf][2] * inv1, oacc[nf][3] * inv1, hh, ll);
        *(uint32_t*)(Oh + o1) = hh;
        *(uint32_t*)(Ol + o1) = ll;
    }
}

// ---------------------------------------------------------------------------
extern "C" void kernel_launch(void* const* d_in, const int* in_sizes, int n_in,
                              void* d_out, int out_size)
{
    const float* X  = (const float*)d_in[0];
    const float* fc = (const float*)d_in[1];
    const float* fs = (const float*)d_in[2];
    // d_in[3] atten_mask unused: exactly causal, applied analytically
    const float* Wq = (const float*)d_in[4];
    const float* Wk = (const float*)d_in[5];
    const float* Wv = (const float*)d_in[6];
    const float* Wo = (const float*)d_in[7];
    const float* qw = (const float*)d_in[8];
    const float* kw = (const float*)d_in[9];
    float* out = (float*)d_out;

    float *q, *k, *v;
    f16 *bf, *bf2;
    cudaGetSymbolAddress((void**)&q, g_q);
    cudaGetSymbolAddress((void**)&k, g_k);
    cudaGetSymbolAddress((void**)&v, g_v);
    cudaGetSymbolAddress((void**)&bf, g_bf);
    cudaGetSymbolAddress((void**)&bf2, g_bf2);

    cudaFuncSetAttribute(qkv_gemm, cudaFuncAttributeMaxDynamicSharedMemorySize,
                         MG2_SMEM);
    cudaFuncSetAttribute(mma_gemm2, cudaFuncAttributeMaxDynamicSharedMemorySize,
                         MG2_SMEM);
    cudaFuncSetAttribute(flash_mma2, cudaFuncAttributeMaxDynamicSharedMemorySize,
                         FH2_SMEM);

    // split X + all weights to f16 hi/lo (one launch)
    split5<<<65536, 256>>>(X, Wq, Wk, Wv, Wo, bf);

    // fused QKV projection (q,k: 3-prod; v: 2-prod)
    qkv_gemm<<<dim3(32, 16), 256, MG2_SMEM>>>(bf, q, k, v);

    // RMSNorm + RoPE for q AND k -> f16 hi/lo (one launch)
    norm_rope_all<<<dim3(S_LEN, NH + NKH), 128>>>(q, k, qw, kw, fc, fs, bf2);

    // k_new / v_new tail outputs
    kvnew_kernel<<<4, 256>>>(bf2 + OFF_KH, bf2 + OFF_KL, v, out);

    // V transpose + split (hi only)
    vtrans_split<<<dim3(64, 4, 8), dim3(32, 8)>>>(v, bf2 + OFF_VTH);

    // GQA-paired flash attention (scores 3-prod, PV 2-prod)
    flash_mma2<<<dim3(32, 8), 256, FH2_SMEM>>>(
        bf2 + OFF_QH, bf2 + OFF_QL, bf2 + OFF_KH, bf2 + OFF_KL,
        bf2 + OFF_VTH, bf + OFF_ATH, bf + OFF_ATL);

    // output projection (2-prod) directly into d_out
    mma_gemm2<<<dim3(16, 16), 256, MG2_SMEM>>>(bf + OFF_ATH, bf + OFF_ATL,
                                               bf + OFF_WOH, bf + OFF_WOL,
                                               out, HID, NH * HD);
}